// round 9
// baseline (speedup 1.0000x reference)
#include <cuda_runtime.h>
#include <math.h>

// Problem dims
#define BB 128
#define SS 1024
#define QMAX 5001          // q ids 0..5000
#define MSLOT 64
#define KDIM 128
#define VDIM 256
#define FDIM 128
#define NT 131072          // BB*SS

typedef unsigned long long ull;

// ---------------- scratch (static device arrays: no allocation) -------------
__device__ float g_Wtab[QMAX * MSLOT];          // softmax(qe @ K^T) per q
__device__ float g_bvE2[512];                   // b_value@[We|Wa] + [b_erase|b_add]
__device__ float g_EAtab[QMAX * 4 * 512];       // [q][r][ -erase(256) | add(256) ]  (erase NEGATED)
__device__ float g_QStab[QMAX * FDIM];          // qe @ W_summary[256:384] + b_summary
__device__ float g_betatab[QMAX * 3];           // qe @ W_beta + b_beta
__device__ float g_qdtab[QMAX];                 // qe @ W_disc[128:256]
__device__ float g_read[(size_t)NT * VDIM];     // per-step memory reads
__device__ float g_summary[(size_t)NT * FDIM];  // tanh summary

// ---------------- packed f32x2 helpers --------------------------------------
__device__ __forceinline__ ull pack2(float lo, float hi) {
    ull d; asm("mov.b64 %0, {%1, %2};" : "=l"(d) : "f"(lo), "f"(hi)); return d;
}
__device__ __forceinline__ void unpack2(ull v, float& lo, float& hi) {
    asm("mov.b64 {%0, %1}, %2;" : "=f"(lo), "=f"(hi) : "l"(v));
}
__device__ __forceinline__ ull fma2(ull a, ull b, ull c) {
    ull d; asm("fma.rn.f32x2 %0, %1, %2, %3;" : "=l"(d) : "l"(a), "l"(b), "l"(c));
    return d;
}
__device__ __forceinline__ ull add2(ull a, ull b) {
    ull d; asm("add.rn.f32x2 %0, %1, %2;" : "=l"(d) : "l"(a), "l"(b));
    return d;
}

__device__ __forceinline__ float sigmoidf_(float x) { return 1.0f / (1.0f + expf(-x)); }
__device__ __forceinline__ float softplusf_(float x) {
    return fmaxf(x, 0.0f) + log1pf(expf(-fabsf(x)));
}

// ---------------- K1: fused wtab + perq (per q); last block: bv + EA row0 ----
__global__ void __launch_bounds__(128) wtab_perq_kernel(const float* __restrict__ qe_table,
                                                        const float* __restrict__ key_memory,
                                                        const float* __restrict__ W_summary,
                                                        const float* __restrict__ b_summary,
                                                        const float* __restrict__ W_beta,
                                                        const float* __restrict__ b_beta,
                                                        const float* __restrict__ W_disc,
                                                        const float* __restrict__ b_value,
                                                        const float* __restrict__ W_erase,
                                                        const float* __restrict__ W_add,
                                                        const float* __restrict__ b_erase,
                                                        const float* __restrict__ b_add) {
    int t = threadIdx.x;
    if (blockIdx.x == QMAX) {   // bv role: bvE2 + EAtab[q=0] (erase negated)
        for (int j = t; j < 512; j += 128) {
            const float* W = (j < 256) ? (W_erase + j) : (W_add + (j - 256));
            float a = 0.0f;
            for (int k = 0; k < 256; k++) a = fmaf(b_value[k], W[k * 256], a);
            float bias = (j < 256) ? b_erase[j] : b_add[j - 256];
            float x = a + bias;
            g_bvE2[j] = x;
            float act = (j < 256) ? -sigmoidf_(x) : tanhf(x);
            #pragma unroll
            for (int rr = 0; rr < 4; rr++) g_EAtab[(size_t)rr * 512 + j] = act;
        }
        return;
    }
    int q = blockIdx.x;
    __shared__ float qe[KDIM];
    __shared__ float sh_d[MSLOT];
    __shared__ float sh_e[MSLOT];
    qe[t] = qe_table[q * KDIM + t];
    __syncthreads();
    float d = 0.0f;
    if (t < MSLOT) {
        #pragma unroll 8
        for (int k = 0; k < KDIM; k++) d = fmaf(qe[k], key_memory[t * KDIM + k], d);
        sh_d[t] = d;
    }
    __syncthreads();
    if (t < MSLOT) {
        float mx = -1e30f;
        #pragma unroll 8
        for (int i = 0; i < MSLOT; i++) mx = fmaxf(mx, sh_d[i]);
        sh_e[t] = expf(d - mx);
    }
    __syncthreads();
    if (t < MSLOT) {
        float sum = 0.0f;
        #pragma unroll 8
        for (int i = 0; i < MSLOT; i++) sum += sh_e[i];
        g_Wtab[q * MSLOT + t] = sh_e[t] / sum;
    }
    // perq projections
    {
        float acc = b_summary[t];
        #pragma unroll 8
        for (int dd = 0; dd < KDIM; dd++)
            acc = fmaf(qe[dd], W_summary[(256 + dd) * FDIM + t], acc);
        g_QStab[q * FDIM + t] = acc;
    }
    if (t < 3) {
        float a = b_beta[t];
        for (int dd = 0; dd < KDIM; dd++) a = fmaf(qe[dd], W_beta[dd * 3 + t], a);
        g_betatab[q * 3 + t] = a;
    } else if (t == 4) {
        float a = 0.0f;
        for (int dd = 0; dd < KDIM; dd++) a = fmaf(qe[dd], W_disc[128 + dd], a);
        g_qdtab[q] = a;
    }
}

// ---------------- K2: fused PP-GEMM + EA table (erase negated) ---------------
__global__ void __launch_bounds__(256, 2) ppea_kernel(const float* __restrict__ Wv,
                                                      const float* __restrict__ We,
                                                      const float* __restrict__ Wa) {
    const int K = 256;
    __shared__ float As1[8][128];  // duplicated pairs: 64 rows
    __shared__ float As2[8][128];
    __shared__ float Bs[8][128];
    int tid = threadIdx.x;
    int row0 = blockIdx.y * 64, col0 = blockIdx.x * 128;
    int lrow = (tid & 127) >> 1, ak4 = (tid & 1) * 4;
    int bK = tid >> 5, bCol = (tid & 31) * 4;
    int tx = tid & 15, ty = tid >> 4;
    ull acc1[4][4], acc2[4][4];
    #pragma unroll
    for (int i = 0; i < 4; i++)
        #pragma unroll
        for (int j = 0; j < 4; j++) { acc1[i][j] = 0ull; acc2[i][j] = 0ull; }

    int gr = row0 + lrow;
    bool valid = (gr < 5000);
    const float* aptr = Wv + ((tid < 128) ? (size_t)gr * K : (size_t)(5000 + gr) * K);
    for (int k0 = 0; k0 < K; k0 += 8) {
        float4 av = make_float4(0, 0, 0, 0);
        if (valid) av = __ldg((const float4*)(aptr + k0 + ak4));
        float (*As)[128] = (tid < 128) ? As1 : As2;
        *(float2*)&As[ak4 + 0][2 * lrow] = make_float2(av.x, av.x);
        *(float2*)&As[ak4 + 1][2 * lrow] = make_float2(av.y, av.y);
        *(float2*)&As[ak4 + 2][2 * lrow] = make_float2(av.z, av.z);
        *(float2*)&As[ak4 + 3][2 * lrow] = make_float2(av.w, av.w);
        int j = col0 + bCol;
        const float* bp = (j < 256) ? (We + (k0 + bK) * 256 + j)
                                    : (Wa + (k0 + bK) * 256 + (j - 256));
        *(float4*)&Bs[bK][bCol] = __ldg((const float4*)bp);
        __syncthreads();
        #pragma unroll
        for (int kk = 0; kk < 8; kk++) {
            const ulonglong2* r1p = (const ulonglong2*)&As1[kk][8 * ty];
            const ulonglong2* r2p = (const ulonglong2*)&As2[kk][8 * ty];
            const ulonglong2* rbp = (const ulonglong2*)&Bs[kk][8 * tx];
            ulonglong2 a1v0 = r1p[0], a1v1 = r1p[1];
            ulonglong2 a2v0 = r2p[0], a2v1 = r2p[1];
            ulonglong2 b0 = rbp[0], b1 = rbp[1];
            ull ra1[4] = {a1v0.x, a1v0.y, a1v1.x, a1v1.y};
            ull ra2[4] = {a2v0.x, a2v0.y, a2v1.x, a2v1.y};
            ull rb[4]  = {b0.x, b0.y, b1.x, b1.y};
            #pragma unroll
            for (int i = 0; i < 4; i++)
                #pragma unroll
                for (int jp = 0; jp < 4; jp++) {
                    acc1[i][jp] = fma2(ra1[i], rb[jp], acc1[i][jp]);
                    acc2[i][jp] = fma2(ra2[i], rb[jp], acc2[i][jp]);
                }
        }
        __syncthreads();
    }
    bool is_erase = (col0 < 256);
    int cbase = col0 + tx * 8;
    float4 bv0 = *(const float4*)&g_bvE2[cbase];
    float4 bv1 = *(const float4*)&g_bvE2[cbase + 4];
    #pragma unroll
    for (int i = 0; i < 4; i++) {
        int row = ty * 4 + i;
        int q = row0 + row;            // q_id - 1
        if (q >= 5000) continue;
        float c1[8], c2[8];
        #pragma unroll
        for (int jp = 0; jp < 4; jp++) {
            unpack2(acc1[i][jp], c1[2 * jp], c1[2 * jp + 1]);
            unpack2(acc2[i][jp], c2[2 * jp], c2[2 * jp + 1]);
        }
        float x1[8];
        x1[0] = c1[0] + bv0.x; x1[1] = c1[1] + bv0.y;
        x1[2] = c1[2] + bv0.z; x1[3] = c1[3] + bv0.w;
        x1[4] = c1[4] + bv1.x; x1[5] = c1[5] + bv1.y;
        x1[6] = c1[6] + bv1.z; x1[7] = c1[7] + bv1.w;
        #pragma unroll
        for (int rr = 0; rr < 4; rr++) {
            float sc = (float)rr * (1.0f / 3.0f);
            float o[8];
            #pragma unroll
            for (int u = 0; u < 8; u++) {
                float x = fmaf(sc, c2[u], x1[u]);
                o[u] = is_erase ? -sigmoidf_(x) : tanhf(x);   // erase NEGATED
            }
            float* dst = &g_EAtab[((size_t)(q + 1) * 4 + rr) * 512 + cbase];
            *(float4*)dst       = make_float4(o[0], o[1], o[2], o[3]);
            *(float4*)(dst + 4) = make_float4(o[4], o[5], o[6], o[7]);
        }
    }
}

// ---------------- K3: scan, v-packed lanes -----------------------------------
// 128 CTAs, 512 threads. Thread owns v-pair (2p,2p+1) x 16 m (quarter*16..+16).
// R[i] lanes = (Mv[m][v0], Mv[m][v1]). w duplicated (w,w) in smem ring.
// e pre-negated in table so step is pure fma2; read acc stays packed over v.
__device__ __forceinline__ void ea_pref(int q, int r, int p, ull& ne, ull& aa) {
    const ull* ea = (const ull*)(g_EAtab + (size_t)(q * 4 + r) * 512);
    ne = __ldg(ea + p);           // (-e_v0, -e_v1)
    aa = __ldg(ea + 128 + p);     // ( a_v0,  a_v1)
}

__device__ __forceinline__ void scan_step(ull* R, const float* wrow,
                                          ull ne, ull aa, int quarter, float* outp) {
    ull acc_a = 0ull, acc_b = 0ull;
    const ulonglong2* wp = (const ulonglong2*)wrow;
    #pragma unroll
    for (int i = 0; i < 8; i++) {
        ulonglong2 wv = wp[i];               // ((w_m,w_m),(w_m1,w_m1))
        ull t0 = fma2(ne, R[2 * i], aa);
        acc_a  = fma2(wv.x, R[2 * i], acc_a);
        R[2 * i] = fma2(wv.x, t0, R[2 * i]);
        ull t1 = fma2(ne, R[2 * i + 1], aa);
        acc_b  = fma2(wv.y, R[2 * i + 1], acc_b);
        R[2 * i + 1] = fma2(wv.y, t1, R[2 * i + 1]);
    }
    ull acc = add2(acc_a, acc_b);
    acc = add2(acc, __shfl_xor_sync(0xffffffffu, acc, 1));
    acc = add2(acc, __shfl_xor_sync(0xffffffffu, acc, 2));
    if (quarter == 0) *(ull*)outp = acc;
}

__global__ void __launch_bounds__(512) scan_kernel(const int* __restrict__ q_data,
                                                   const int* __restrict__ r_data,
                                                   const float* __restrict__ initMv) {
    const int b = blockIdx.x;
    const int tid = threadIdx.x;
    const int quarter = tid & 3;
    const int p = tid >> 2;

    __shared__ int q_sh[SS + 8];
    __shared__ int r_sh[SS + 8];
    __shared__ float wring[64 * 2 * MSLOT];   // 64 steps x 128 floats (dup) = 32KB

    for (int i = tid; i < SS; i += 512) {
        q_sh[i] = q_data[b * SS + i];
        r_sh[i] = r_data[b * SS + i];
    }
    if (tid < 8) {
        q_sh[SS + tid] = q_data[b * SS + SS - 1];
        r_sh[SS + tid] = r_data[b * SS + SS - 1];
    }

    ull R[16];
    #pragma unroll
    for (int i = 0; i < 16; i++) {
        int m = quarter * 16 + i;
        R[i] = *(const ull*)(initMv + (size_t)m * VDIM + 2 * p);
    }
    __syncthreads();

    ull neA, aaA, neB, aaB, neC, aaC, neD, aaD;
    ea_pref(q_sh[0], r_sh[0], p, neA, aaA);
    ea_pref(q_sh[1], r_sh[1], p, neB, aaB);
    ea_pref(q_sh[2], r_sh[2], p, neC, aaC);

    float* rdbase = g_read + (((size_t)b << 10)) * VDIM + 2 * p;
    const int qoff = quarter * 32;

    #pragma unroll 1
    for (int c = 0; c < 16; c++) {
        __syncthreads();   // prior chunk fully consumed before ring overwrite
        {   // cooperative refill with duplication: slot = tid>>3, j = tid&7
            int sl = tid >> 3;
            int j = tid & 7;
            const float* src = g_Wtab + q_sh[c * 64 + sl] * MSLOT + j * 8;
            float4 v0 = __ldg((const float4*)src);
            float4 v1 = __ldg((const float4*)(src + 4));
            float* dst = &wring[sl * 128 + j * 16];
            *(float4*)(dst + 0)  = make_float4(v0.x, v0.x, v0.y, v0.y);
            *(float4*)(dst + 4)  = make_float4(v0.z, v0.z, v0.w, v0.w);
            *(float4*)(dst + 8)  = make_float4(v1.x, v1.x, v1.y, v1.y);
            *(float4*)(dst + 12) = make_float4(v1.z, v1.z, v1.w, v1.w);
        }
        __syncthreads();
        int base = c * 64;
        #pragma unroll 1
        for (int k = 0; k < 16; k++) {
            int s = base + k * 4;
            ea_pref(q_sh[s + 3], r_sh[s + 3], p, neD, aaD);
            scan_step(R, &wring[((s) & 63) * 128 + qoff], neA, aaA, quarter,
                      rdbase + (size_t)s * VDIM);
            ea_pref(q_sh[s + 4], r_sh[s + 4], p, neA, aaA);
            scan_step(R, &wring[((s + 1) & 63) * 128 + qoff], neB, aaB, quarter,
                      rdbase + (size_t)(s + 1) * VDIM);
            ea_pref(q_sh[s + 5], r_sh[s + 5], p, neB, aaB);
            scan_step(R, &wring[((s + 2) & 63) * 128 + qoff], neC, aaC, quarter,
                      rdbase + (size_t)(s + 2) * VDIM);
            ea_pref(q_sh[s + 6], r_sh[s + 6], p, neC, aaC);
            scan_step(R, &wring[((s + 3) & 63) * 128 + qoff], neD, aaD, quarter,
                      rdbase + (size_t)(s + 3) * VDIM);
        }
    }
}

// ---------------- K4: summary SGEMM (131072x256 @ 256x128), LDS.128, tanh ----
__global__ void __launch_bounds__(256, 2) sgemm_sum_kernel(const int* __restrict__ q_data,
                                                           const float* __restrict__ W_summary) {
    const int K = 256, N = 128;
    __shared__ float As[8][256];   // duplicated
    __shared__ float Bs[8][128];
    __shared__ int qrow_s[128];
    int tid = threadIdx.x;
    int row0 = blockIdx.x * 128;
    if (tid < 128) qrow_s[tid] = q_data[row0 + tid];
    int aRow = tid >> 1, aK4 = (tid & 1) * 4;
    int bK = tid >> 5, bCol = (tid & 31) * 4;
    int tx = tid & 15, ty = tid >> 4;
    ull acc2[8][4];
    #pragma unroll
    for (int i = 0; i < 8; i++)
        #pragma unroll
        for (int j = 0; j < 4; j++) acc2[i][j] = 0ull;

    const float* A = g_read;
    for (int k0 = 0; k0 < K; k0 += 8) {
        float4 av = __ldg((const float4*)(A + (size_t)(row0 + aRow) * K + k0 + aK4));
        *(float2*)&As[aK4 + 0][2 * aRow] = make_float2(av.x, av.x);
        *(float2*)&As[aK4 + 1][2 * aRow] = make_float2(av.y, av.y);
        *(float2*)&As[aK4 + 2][2 * aRow] = make_float2(av.z, av.z);
        *(float2*)&As[aK4 + 3][2 * aRow] = make_float2(av.w, av.w);
        *(float4*)&Bs[bK][bCol] = __ldg((const float4*)(W_summary + (k0 + bK) * N + bCol));
        __syncthreads();
        #pragma unroll
        for (int kk = 0; kk < 8; kk++) {
            const ulonglong2* rap = (const ulonglong2*)&As[kk][16 * ty];
            const ulonglong2* rbp = (const ulonglong2*)&Bs[kk][8 * tx];
            ulonglong2 a0 = rap[0], a1 = rap[1], a2 = rap[2], a3 = rap[3];
            ulonglong2 b0 = rbp[0], b1 = rbp[1];
            ull ra[8] = {a0.x, a0.y, a1.x, a1.y, a2.x, a2.y, a3.x, a3.y};
            ull rb[4] = {b0.x, b0.y, b1.x, b1.y};
            #pragma unroll
            for (int i = 0; i < 8; i++)
                #pragma unroll
                for (int jp = 0; jp < 4; jp++)
                    acc2[i][jp] = fma2(ra[i], rb[jp], acc2[i][jp]);
        }
        __syncthreads();
    }
    int cbase = tx * 8;
    #pragma unroll
    for (int i = 0; i < 8; i++) {
        int rl = ty * 8 + i;
        int r = row0 + rl;
        int q = qrow_s[rl];
        const float* qs = g_QStab + q * FDIM + cbase;
        float4 q0 = __ldg((const float4*)qs);
        float4 q1 = __ldg((const float4*)(qs + 4));
        float v[8];
        #pragma unroll
        for (int jp = 0; jp < 4; jp++) unpack2(acc2[i][jp], v[2 * jp], v[2 * jp + 1]);
        float4 o0 = make_float4(tanhf(v[0] + q0.x), tanhf(v[1] + q0.y),
                                tanhf(v[2] + q0.z), tanhf(v[3] + q0.w));
        float4 o1 = make_float4(tanhf(v[4] + q1.x), tanhf(v[5] + q1.y),
                                tanhf(v[6] + q1.z), tanhf(v[7] + q1.w));
        float* dst = &g_summary[(size_t)r * N + cbase];
        *(float4*)dst       = o0;
        *(float4*)(dst + 4) = o1;
    }
}

// ---------------- K5: per-token head (theta/alpha/CORAL), 32 tokens/warp -----
__global__ void __launch_bounds__(256) head_kernel(const int* __restrict__ q_data,
                                                   const float* __restrict__ W_theta,
                                                   const float* __restrict__ b_theta,
                                                   const float* __restrict__ W_disc,
                                                   const float* __restrict__ b_disc,
                                                   const float* __restrict__ W_c1,
                                                   const float* __restrict__ b_c1,
                                                   const float* __restrict__ W_c2,
                                                   const float* __restrict__ b_c2,
                                                   const float* __restrict__ coral_w,
                                                   const float* __restrict__ coral_b,
                                                   float* __restrict__ out) {
    __shared__ float sWc1[5 * 64], sBc1[64], sWc2[64 * 32], sBc2[32], sCw[32];
    __shared__ float sWth[128], sWd[128];
    __shared__ float h1s[8][64];
    int tid = threadIdx.x;
    for (int i = tid; i < 320; i += 256) sWc1[i] = W_c1[i];
    for (int i = tid; i < 2048; i += 256) sWc2[i] = W_c2[i];
    if (tid < 64) sBc1[tid] = b_c1[tid];
    if (tid < 32) { sBc2[tid] = b_c2[tid]; sCw[tid] = coral_w[tid]; }
    if (tid < 128) { sWth[tid] = W_theta[tid]; sWd[tid] = W_disc[tid]; }
    __syncthreads();

    int warp = tid >> 5, lane = tid & 31;
    float bth = b_theta[0], bd = b_disc[0];
    float cb0 = coral_b[0], cb1 = coral_b[1], cb2 = coral_b[2];
    float wth0 = sWth[lane], wth1 = sWth[lane + 32], wth2 = sWth[lane + 64], wth3 = sWth[lane + 96];
    float wd0 = sWd[lane], wd1 = sWd[lane + 32], wd2 = sWd[lane + 64], wd3 = sWd[lane + 96];
    float cw = sCw[lane];

    const int TOK = 32;
    size_t base = ((size_t)blockIdx.x * 8 + warp) * TOK;
    for (int t = 0; t < TOK; t++) {
        size_t n = base + t;
        const float* srow = g_summary + n * FDIM;
        float s0 = __ldg(srow + lane), s1 = __ldg(srow + lane + 32);
        float s2 = __ldg(srow + lane + 64), s3 = __ldg(srow + lane + 96);
        float th = s0 * wth0 + s1 * wth1 + s2 * wth2 + s3 * wth3;
        float dp = s0 * wd0 + s1 * wd1 + s2 * wd2 + s3 * wd3;
        #pragma unroll
        for (int o = 16; o; o >>= 1) {
            th += __shfl_xor_sync(0xffffffffu, th, o);
            dp += __shfl_xor_sync(0xffffffffu, dp, o);
        }
        float theta = (th + bth) * 3.0f;
        int q = q_data[n];
        float alpha = softplusf_(dp + g_qdtab[q] + bd);
        float be0 = g_betatab[q * 3 + 0];
        float be1 = g_betatab[q * 3 + 1];
        float be2 = g_betatab[q * 3 + 2];
        float feat[5] = {theta, alpha, be0, be1, be2};

        float h1a = sBc1[lane], h1b = sBc1[lane + 32];
        #pragma unroll
        for (int i = 0; i < 5; i++) {
            h1a = fmaf(feat[i], sWc1[i * 64 + lane], h1a);
            h1b = fmaf(feat[i], sWc1[i * 64 + lane + 32], h1b);
        }
        h1s[warp][lane] = fmaxf(h1a, 0.0f);
        h1s[warp][lane + 32] = fmaxf(h1b, 0.0f);
        __syncwarp();
        float h2 = sBc2[lane];
        #pragma unroll
        for (int i = 0; i < 64; i++) h2 = fmaf(h1s[warp][i], sWc2[i * 32 + lane], h2);
        h2 = fmaxf(h2, 0.0f);
        float lg = h2 * cw;
        #pragma unroll
        for (int o = 16; o; o >>= 1) lg += __shfl_xor_sync(0xffffffffu, lg, o);

        if (lane == 0) {
            float l0 = lg + cb0, l1 = lg + cb1, l2 = lg + cb2;
            float c1 = sigmoidf_(l0);
            float c2 = c1 * sigmoidf_(l1);
            float c3 = c2 * sigmoidf_(l2);
            const size_t N = NT;
            out[n] = theta;
            out[N + n * 3 + 0] = be0;
            out[N + n * 3 + 1] = be1;
            out[N + n * 3 + 2] = be2;
            out[4 * N + n] = alpha;
            out[5 * N + n * 4 + 0] = 1.0f - c1;
            out[5 * N + n * 4 + 1] = c1 - c2;
            out[5 * N + n * 4 + 2] = c2 - c3;
            out[5 * N + n * 4 + 3] = c3;
            out[9 * N + n * 3 + 0] = l0;
            out[9 * N + n * 3 + 1] = l1;
            out[9 * N + n * 3 + 2] = l2;
        }
        __syncwarp();
    }
}

// ---------------- launch -----------------------------------------------------
extern "C" void kernel_launch(void* const* d_in, const int* in_sizes, int n_in,
                              void* d_out, int out_size) {
    const int*   q_data   = (const int*)d_in[0];
    const int*   r_data   = (const int*)d_in[1];
    const float* qe_table = (const float*)d_in[2];
    const float* key_mem  = (const float*)d_in[3];
    const float* initMv   = (const float*)d_in[4];
    const float* W_value  = (const float*)d_in[5];
    const float* b_value  = (const float*)d_in[6];
    const float* W_erase  = (const float*)d_in[7];
    const float* b_erase  = (const float*)d_in[8];
    const float* W_add    = (const float*)d_in[9];
    const float* b_add    = (const float*)d_in[10];
    const float* W_summary= (const float*)d_in[11];
    const float* b_summary= (const float*)d_in[12];
    const float* W_theta  = (const float*)d_in[13];
    const float* b_theta  = (const float*)d_in[14];
    const float* W_beta   = (const float*)d_in[15];
    const float* b_beta   = (const float*)d_in[16];
    const float* W_disc   = (const float*)d_in[17];
    const float* b_disc   = (const float*)d_in[18];
    const float* W_c1     = (const float*)d_in[19];
    const float* b_c1     = (const float*)d_in[20];
    const float* W_c2     = (const float*)d_in[21];
    const float* b_c2     = (const float*)d_in[22];
    const float* coral_w  = (const float*)d_in[23];
    const float* coral_b  = (const float*)d_in[24];
    float* out = (float*)d_out;

    // L1: wtab + perq + bv/EA0
    wtab_perq_kernel<<<QMAX + 1, 128>>>(qe_table, key_mem, W_summary, b_summary,
                                        W_beta, b_beta, W_disc,
                                        b_value, W_erase, W_add, b_erase, b_add);
    // L2: fused PP GEMM + EA table
    {
        dim3 g(4, 79);
        ppea_kernel<<<g, 256>>>(W_value, W_erase, W_add);
    }
    // L3: scan (v-packed)
    scan_kernel<<<BB, 512>>>(q_data, r_data, initMv);
    // L4: summary GEMM (<- ncu capture slot)
    sgemm_sum_kernel<<<NT / 128, 256>>>(q_data, W_summary);
    // L5: head
    head_kernel<<<NT / (8 * 32), 256>>>(q_data, W_theta, b_theta, W_disc, b_disc,
                                        W_c1, b_c1, W_c2, b_c2, coral_w, coral_b, out);
}

// round 12
// speedup vs baseline: 1.1325x; 1.1325x over previous
#include <cuda_runtime.h>
#include <math.h>

// Problem dims
#define BB 128
#define SS 1024
#define QMAX 5001          // q ids 0..5000
#define MSLOT 64
#define KDIM 128
#define VDIM 256
#define FDIM 128
#define NT 131072          // BB*SS

typedef unsigned long long ull;

// ---------------- scratch (static device arrays: no allocation) -------------
__device__ float g_Wtab[QMAX * MSLOT];          // softmax(qe @ K^T) per q
__device__ float g_bvE2[512];                   // b_value@[We|Wa] + [b_erase|b_add]
__device__ float g_EAtab[QMAX * 4 * 512];       // [q][r][ erase(256) | add(256) ]
__device__ float g_QStab[QMAX * FDIM];          // qe @ W_summary[256:384] + b_summary
__device__ float g_betatab[QMAX * 3];           // qe @ W_beta + b_beta
__device__ float g_qdtab[QMAX];                 // qe @ W_disc[128:256]
__device__ float g_read[(size_t)NT * VDIM];     // per-step memory reads
__device__ float g_summary[(size_t)NT * FDIM];  // tanh summary

// ---------------- packed f32x2 helpers --------------------------------------
__device__ __forceinline__ ull pack2(float lo, float hi) {
    ull d; asm("mov.b64 %0, {%1, %2};" : "=l"(d) : "f"(lo), "f"(hi)); return d;
}
__device__ __forceinline__ void unpack2(ull v, float& lo, float& hi) {
    asm("mov.b64 {%0, %1}, %2;" : "=f"(lo), "=f"(hi) : "l"(v));
}
__device__ __forceinline__ ull fma2(ull a, ull b, ull c) {
    ull d; asm("fma.rn.f32x2 %0, %1, %2, %3;" : "=l"(d) : "l"(a), "l"(b), "l"(c));
    return d;
}

__device__ __forceinline__ float sigmoidf_(float x) { return 1.0f / (1.0f + expf(-x)); }
__device__ __forceinline__ float softplusf_(float x) {
    return fmaxf(x, 0.0f) + log1pf(expf(-fabsf(x)));
}

// ---------------- K1: fused wtab + perq (per q); last block: bv + EA row0 ----
__global__ void __launch_bounds__(128) wtab_perq_kernel(const float* __restrict__ qe_table,
                                                        const float* __restrict__ key_memory,
                                                        const float* __restrict__ b_value,
                                                        const float* __restrict__ W_erase,
                                                        const float* __restrict__ W_add,
                                                        const float* __restrict__ b_erase,
                                                        const float* __restrict__ b_add,
                                                        const float* __restrict__ W_summary,
                                                        const float* __restrict__ b_summary,
                                                        const float* __restrict__ W_beta,
                                                        const float* __restrict__ b_beta,
                                                        const float* __restrict__ W_disc) {
    int t = threadIdx.x;
    if (blockIdx.x == QMAX) {   // bv role: bvE2 + EAtab[q=0]
        for (int j = t; j < 512; j += 128) {
            const float* W = (j < 256) ? (W_erase + j) : (W_add + (j - 256));
            float a = 0.0f;
            for (int k = 0; k < 256; k++) a = fmaf(b_value[k], W[k * 256], a);
            float bias = (j < 256) ? b_erase[j] : b_add[j - 256];
            float x = a + bias;
            g_bvE2[j] = x;
            float act = (j < 256) ? sigmoidf_(x) : tanhf(x);
            #pragma unroll
            for (int rr = 0; rr < 4; rr++) g_EAtab[(size_t)rr * 512 + j] = act;
        }
        return;
    }
    int q = blockIdx.x;
    __shared__ float qe[KDIM];
    __shared__ float sh_d[MSLOT];
    __shared__ float sh_e[MSLOT];
    qe[t] = qe_table[q * KDIM + t];
    __syncthreads();
    float d = 0.0f;
    if (t < MSLOT) {
        #pragma unroll 8
        for (int k = 0; k < KDIM; k++) d = fmaf(qe[k], key_memory[t * KDIM + k], d);
        sh_d[t] = d;
    }
    __syncthreads();
    if (t < MSLOT) {
        float mx = -1e30f;
        #pragma unroll 8
        for (int i = 0; i < MSLOT; i++) mx = fmaxf(mx, sh_d[i]);
        sh_e[t] = expf(d - mx);
    }
    __syncthreads();
    if (t < MSLOT) {
        float sum = 0.0f;
        #pragma unroll 8
        for (int i = 0; i < MSLOT; i++) sum += sh_e[i];
        g_Wtab[q * MSLOT + t] = sh_e[t] / sum;
    }
    // perq projections
    {
        float acc = b_summary[t];
        #pragma unroll 8
        for (int dd = 0; dd < KDIM; dd++)
            acc = fmaf(qe[dd], W_summary[(256 + dd) * FDIM + t], acc);
        g_QStab[q * FDIM + t] = acc;
    }
    if (t < 3) {
        float a = b_beta[t];
        for (int dd = 0; dd < KDIM; dd++) a = fmaf(qe[dd], W_beta[dd * 3 + t], a);
        g_betatab[q * 3 + t] = a;
    } else if (t == 4) {
        float a = 0.0f;
        for (int dd = 0; dd < KDIM; dd++) a = fmaf(qe[dd], W_disc[128 + dd], a);
        g_qdtab[q] = a;
    }
}

// ---------------- K2: fused PP-GEMM + EA table (reg double-buffered) ---------
// C1[q,:] = Wv[q]·[We|Wa], C2[q,:] = Wv[5000+q]·[We|Wa]  (q = q_id-1, 0..4999)
// EA[q+1][r][col] = act( C1 + bvE2 + (r/3)·C2 )
__global__ void __launch_bounds__(256, 2) ppea_kernel(const float* __restrict__ Wv,
                                                      const float* __restrict__ We,
                                                      const float* __restrict__ Wa) {
    const int K = 256;
    __shared__ float As1[8][128];  // duplicated pairs: 64 rows
    __shared__ float As2[8][128];
    __shared__ float Bs[8][128];
    int tid = threadIdx.x;
    int row0 = blockIdx.y * 64, col0 = blockIdx.x * 128;
    int lrow = (tid & 127) >> 1, ak4 = (tid & 1) * 4;
    int bK = tid >> 5, bCol = (tid & 31) * 4;
    int tx = tid & 15, ty = tid >> 4;
    ull acc1[4][4], acc2[4][4];
    #pragma unroll
    for (int i = 0; i < 4; i++)
        #pragma unroll
        for (int j = 0; j < 4; j++) { acc1[i][j] = 0ull; acc2[i][j] = 0ull; }

    int gr = row0 + lrow;
    bool valid = (gr < 5000);
    const float* aptr = Wv + ((tid < 128) ? (size_t)gr * K : (size_t)(5000 + gr) * K);
    int jcol = col0 + bCol;
    const float* bbase = (jcol < 256) ? (We + jcol) : (Wa + (jcol - 256));

    float4 av = make_float4(0, 0, 0, 0);
    if (valid) av = __ldg((const float4*)(aptr + ak4));
    float4 bv = __ldg((const float4*)(bbase + bK * 256));

    for (int k0 = 0; k0 < K; k0 += 8) {
        float (*As)[128] = (tid < 128) ? As1 : As2;
        *(float2*)&As[ak4 + 0][2 * lrow] = make_float2(av.x, av.x);
        *(float2*)&As[ak4 + 1][2 * lrow] = make_float2(av.y, av.y);
        *(float2*)&As[ak4 + 2][2 * lrow] = make_float2(av.z, av.z);
        *(float2*)&As[ak4 + 3][2 * lrow] = make_float2(av.w, av.w);
        *(float4*)&Bs[bK][bCol] = bv;
        __syncthreads();
        if (k0 + 8 < K) {   // prefetch next k-block (overlaps compute)
            if (valid) av = __ldg((const float4*)(aptr + k0 + 8 + ak4));
            bv = __ldg((const float4*)(bbase + (k0 + 8 + bK) * 256));
        }
        #pragma unroll
        for (int kk = 0; kk < 8; kk++) {
            ull ra1[4], ra2[4], rb[4];
            #pragma unroll
            for (int i = 0; i < 4; i++) {
                ra1[i] = *(const ull*)&As1[kk][2 * (ty * 4 + i)];
                ra2[i] = *(const ull*)&As2[kk][2 * (ty * 4 + i)];
            }
            #pragma unroll
            for (int jp = 0; jp < 4; jp++) rb[jp] = *(const ull*)&Bs[kk][jp * 32 + tx * 2];
            #pragma unroll
            for (int i = 0; i < 4; i++)
                #pragma unroll
                for (int jp = 0; jp < 4; jp++) {
                    acc1[i][jp] = fma2(ra1[i], rb[jp], acc1[i][jp]);
                    acc2[i][jp] = fma2(ra2[i], rb[jp], acc2[i][jp]);
                }
        }
        __syncthreads();
    }
    bool is_erase = (col0 < 256);
    #pragma unroll
    for (int i = 0; i < 4; i++) {
        int row = ty * 4 + i;
        int q = row0 + row;            // q_id - 1
        if (q >= 5000) continue;
        #pragma unroll
        for (int jp = 0; jp < 4; jp++) {
            int c = col0 + jp * 32 + tx * 2;
            float c1lo, c1hi, c2lo, c2hi;
            unpack2(acc1[i][jp], c1lo, c1hi);
            unpack2(acc2[i][jp], c2lo, c2hi);
            float blo = g_bvE2[c], bhi = g_bvE2[c + 1];
            float x1lo = c1lo + blo, x1hi = c1hi + bhi;
            #pragma unroll
            for (int rr = 0; rr < 4; rr++) {
                float sc = (float)rr * (1.0f / 3.0f);
                float xlo = fmaf(sc, c2lo, x1lo);
                float xhi = fmaf(sc, c2hi, x1hi);
                float olo = is_erase ? sigmoidf_(xlo) : tanhf(xlo);
                float ohi = is_erase ? sigmoidf_(xhi) : tanhf(xhi);
                *(float2*)&g_EAtab[((size_t)(q + 1) * 4 + rr) * 512 + c] = make_float2(olo, ohi);
            }
        }
    }
}

// ---------------- K3: persistent recurrence scan (smem w-ring, f32x2) --------
// 128 CTAs, 512 threads. Thread owns 2 v (2p, 2p+1) x 16 m (8 pairs).
// quarter = tid&3 (m range quarter*16..+16), p = tid>>2.
__device__ __forceinline__ void ea_pref(int q, int r, int p, float2& ee, float2& aa) {
    const float* ea = g_EAtab + (size_t)(q * 4 + r) * 512;
    ee = __ldg((const float2*)(ea + 2 * p));
    aa = __ldg((const float2*)(ea + 256 + 2 * p));
}

__device__ __forceinline__ void scan_step(ull* R0, ull* R1, const float* wrow,
                                          float2 ee, float2 aa,
                                          int quarter, float* outp) {
    ull W[8];
    {
        const ulonglong2* wp = (const ulonglong2*)wrow;
        ulonglong2 t0 = wp[0], t1 = wp[1], t2 = wp[2], t3 = wp[3];
        W[0] = t0.x; W[1] = t0.y; W[2] = t1.x; W[3] = t1.y;
        W[4] = t2.x; W[5] = t2.y; W[6] = t3.x; W[7] = t3.y;
    }
    ull ne0 = pack2(-ee.x, -ee.x), ne1 = pack2(-ee.y, -ee.y);
    ull a20 = pack2(aa.x, aa.x),   a21 = pack2(aa.y, aa.y);
    ull acc0a = 0ull, acc0b = 0ull, acc1a = 0ull, acc1b = 0ull;
    #pragma unroll
    for (int i = 0; i < 4; i++) {
        ull t0 = fma2(ne0, R0[i], a20);
        ull t1 = fma2(ne1, R1[i], a21);
        acc0a = fma2(W[i], R0[i], acc0a);
        acc1a = fma2(W[i], R1[i], acc1a);
        R0[i] = fma2(W[i], t0, R0[i]);
        R1[i] = fma2(W[i], t1, R1[i]);
    }
    #pragma unroll
    for (int i = 4; i < 8; i++) {
        ull t0 = fma2(ne0, R0[i], a20);
        ull t1 = fma2(ne1, R1[i], a21);
        acc0b = fma2(W[i], R0[i], acc0b);
        acc1b = fma2(W[i], R1[i], acc1b);
        R0[i] = fma2(W[i], t0, R0[i]);
        R1[i] = fma2(W[i], t1, R1[i]);
    }
    float x0a, y0a, x0b, y0b, x1a, y1a, x1b, y1b;
    unpack2(acc0a, x0a, y0a); unpack2(acc0b, x0b, y0b);
    unpack2(acc1a, x1a, y1a); unpack2(acc1b, x1b, y1b);
    float rd0 = (x0a + x0b) + (y0a + y0b);
    float rd1 = (x1a + x1b) + (y1a + y1b);
    rd0 += __shfl_xor_sync(0xffffffffu, rd0, 1);
    rd0 += __shfl_xor_sync(0xffffffffu, rd0, 2);
    rd1 += __shfl_xor_sync(0xffffffffu, rd1, 1);
    rd1 += __shfl_xor_sync(0xffffffffu, rd1, 2);
    if (quarter == 0) *(float2*)outp = make_float2(rd0, rd1);
}

__global__ void __launch_bounds__(512) scan_kernel(const int* __restrict__ q_data,
                                                   const int* __restrict__ r_data,
                                                   const float* __restrict__ initMv) {
    const int b = blockIdx.x;
    const int tid = threadIdx.x;
    const int quarter = tid & 3;
    const int p = tid >> 2;

    __shared__ int q_sh[SS + 8];
    __shared__ int r_sh[SS + 8];
    __shared__ float wring[64 * MSLOT];   // 64 steps x 64 floats = 16KB

    for (int i = tid; i < SS; i += 512) {
        q_sh[i] = q_data[b * SS + i];
        r_sh[i] = r_data[b * SS + i];
    }
    if (tid < 8) {
        q_sh[SS + tid] = q_data[b * SS + SS - 1];
        r_sh[SS + tid] = r_data[b * SS + SS - 1];
    }

    ull R0[8], R1[8];
    #pragma unroll
    for (int i = 0; i < 8; i++) {
        int m = quarter * 16 + 2 * i;
        R0[i] = pack2(initMv[m * VDIM + 2 * p],     initMv[(m + 1) * VDIM + 2 * p]);
        R1[i] = pack2(initMv[m * VDIM + 2 * p + 1], initMv[(m + 1) * VDIM + 2 * p + 1]);
    }
    __syncthreads();

    float2 eA, aA, eB, aB, eC, aC, eD, aD;
    ea_pref(q_sh[0], r_sh[0], p, eA, aA);
    ea_pref(q_sh[1], r_sh[1], p, eB, aB);
    ea_pref(q_sh[2], r_sh[2], p, eC, aC);

    float* rdbase = g_read + (((size_t)b << 10)) * VDIM + 2 * p;
    const int qoff = quarter * 16;

    #pragma unroll 1
    for (int c = 0; c < 16; c++) {
        __syncthreads();   // prior chunk fully consumed before ring overwrite
        {   // cooperative refill: 64 steps x 64 floats, 2 float4 per thread
            int u = tid * 2;
            int sl = u >> 4;
            int fi = u & 15;
            const float* src = g_Wtab + q_sh[c * 64 + sl] * MSLOT;
            *(float4*)&wring[sl * MSLOT + fi * 4]       = __ldg((const float4*)(src + fi * 4));
            *(float4*)&wring[sl * MSLOT + (fi + 1) * 4] = __ldg((const float4*)(src + (fi + 1) * 4));
        }
        __syncthreads();
        int base = c * 64;
        #pragma unroll 1
        for (int k = 0; k < 16; k++) {
            int s = base + k * 4;
            ea_pref(q_sh[s + 3], r_sh[s + 3], p, eD, aD);
            scan_step(R0, R1, &wring[((s) & 63) * MSLOT + qoff], eA, aA, quarter,
                      rdbase + (size_t)s * VDIM);
            ea_pref(q_sh[s + 4], r_sh[s + 4], p, eA, aA);
            scan_step(R0, R1, &wring[((s + 1) & 63) * MSLOT + qoff], eB, aB, quarter,
                      rdbase + (size_t)(s + 1) * VDIM);
            ea_pref(q_sh[s + 5], r_sh[s + 5], p, eB, aB);
            scan_step(R0, R1, &wring[((s + 2) & 63) * MSLOT + qoff], eC, aC, quarter,
                      rdbase + (size_t)(s + 2) * VDIM);
            ea_pref(q_sh[s + 6], r_sh[s + 6], p, eC, aC);
            scan_step(R0, R1, &wring[((s + 3) & 63) * MSLOT + qoff], eD, aD, quarter,
                      rdbase + (size_t)(s + 3) * VDIM);
        }
    }
}

// ---------------- K4: summary SGEMM (131072x256 @ 256x128), reg db, tanh -----
__global__ void __launch_bounds__(256, 2) sgemm_sum_kernel(const int* __restrict__ q_data,
                                                           const float* __restrict__ W_summary) {
    const int K = 256, N = 128;
    __shared__ float As[8][256];   // duplicated
    __shared__ float Bs[8][128];
    __shared__ int qrow_s[128];
    int tid = threadIdx.x;
    int row0 = blockIdx.x * 128;
    if (tid < 128) qrow_s[tid] = q_data[row0 + tid];
    int aRow = tid >> 1, aK4 = (tid & 1) * 4;
    int bK = tid >> 5, bCol = (tid & 31) * 4;
    int tx = tid & 15, ty = tid >> 4;
    ull acc2[8][4];
    #pragma unroll
    for (int i = 0; i < 8; i++)
        #pragma unroll
        for (int j = 0; j < 4; j++) acc2[i][j] = 0ull;

    const float* A = g_read + (size_t)(row0 + aRow) * K + aK4;
    float4 av = __ldg((const float4*)A);
    float4 bv = __ldg((const float4*)(W_summary + bK * N + bCol));

    for (int k0 = 0; k0 < K; k0 += 8) {
        *(float2*)&As[aK4 + 0][2 * aRow] = make_float2(av.x, av.x);
        *(float2*)&As[aK4 + 1][2 * aRow] = make_float2(av.y, av.y);
        *(float2*)&As[aK4 + 2][2 * aRow] = make_float2(av.z, av.z);
        *(float2*)&As[aK4 + 3][2 * aRow] = make_float2(av.w, av.w);
        *(float4*)&Bs[bK][bCol] = bv;
        __syncthreads();
        if (k0 + 8 < K) {   // prefetch next k-block (overlaps compute)
            av = __ldg((const float4*)(A + k0 + 8));
            bv = __ldg((const float4*)(W_summary + (k0 + 8 + bK) * N + bCol));
        }
        #pragma unroll
        for (int kk = 0; kk < 8; kk++) {
            ull ra[8], rb[4];
            #pragma unroll
            for (int i = 0; i < 8; i++) ra[i] = *(const ull*)&As[kk][2 * (ty * 8 + i)];
            #pragma unroll
            for (int jp = 0; jp < 4; jp++) rb[jp] = *(const ull*)&Bs[kk][jp * 32 + tx * 2];
            #pragma unroll
            for (int i = 0; i < 8; i++)
                #pragma unroll
                for (int jp = 0; jp < 4; jp++)
                    acc2[i][jp] = fma2(ra[i], rb[jp], acc2[i][jp]);
        }
        __syncthreads();
    }
    #pragma unroll
    for (int i = 0; i < 8; i++) {
        int rl = ty * 8 + i;
        int r = row0 + rl;
        int q = qrow_s[rl];
        const float* qs = g_QStab + q * FDIM;
        #pragma unroll
        for (int jp = 0; jp < 4; jp++) {
            int c = jp * 32 + tx * 2;
            float lo, hi; unpack2(acc2[i][jp], lo, hi);
            *(float2*)&g_summary[(size_t)r * N + c] =
                make_float2(tanhf(lo + __ldg(qs + c)), tanhf(hi + __ldg(qs + c + 1)));
        }
    }
}

// ---------------- K5: per-token head (theta/alpha/CORAL), 32 tokens/warp -----
__global__ void __launch_bounds__(256) head_kernel(const int* __restrict__ q_data,
                                                   const float* __restrict__ W_theta,
                                                   const float* __restrict__ b_theta,
                                                   const float* __restrict__ W_disc,
                                                   const float* __restrict__ b_disc,
                                                   const float* __restrict__ W_c1,
                                                   const float* __restrict__ b_c1,
                                                   const float* __restrict__ W_c2,
                                                   const float* __restrict__ b_c2,
                                                   const float* __restrict__ coral_w,
                                                   const float* __restrict__ coral_b,
                                                   float* __restrict__ out) {
    __shared__ float sWc1[5 * 64], sBc1[64], sWc2[64 * 32], sBc2[32], sCw[32];
    __shared__ float sWth[128], sWd[128];
    __shared__ float h1s[8][64];
    int tid = threadIdx.x;
    for (int i = tid; i < 320; i += 256) sWc1[i] = W_c1[i];
    for (int i = tid; i < 2048; i += 256) sWc2[i] = W_c2[i];
    if (tid < 64) sBc1[tid] = b_c1[tid];
    if (tid < 32) { sBc2[tid] = b_c2[tid]; sCw[tid] = coral_w[tid]; }
    if (tid < 128) { sWth[tid] = W_theta[tid]; sWd[tid] = W_disc[tid]; }
    __syncthreads();

    int warp = tid >> 5, lane = tid & 31;
    float bth = b_theta[0], bd = b_disc[0];
    float cb0 = coral_b[0], cb1 = coral_b[1], cb2 = coral_b[2];
    float wth0 = sWth[lane], wth1 = sWth[lane + 32], wth2 = sWth[lane + 64], wth3 = sWth[lane + 96];
    float wd0 = sWd[lane], wd1 = sWd[lane + 32], wd2 = sWd[lane + 64], wd3 = sWd[lane + 96];
    float cw = sCw[lane];

    const int TOK = 32;
    size_t base = ((size_t)blockIdx.x * 8 + warp) * TOK;
    for (int t = 0; t < TOK; t++) {
        size_t n = base + t;
        const float* srow = g_summary + n * FDIM;
        float s0 = __ldg(srow + lane), s1 = __ldg(srow + lane + 32);
        float s2 = __ldg(srow + lane + 64), s3 = __ldg(srow + lane + 96);
        float th = s0 * wth0 + s1 * wth1 + s2 * wth2 + s3 * wth3;
        float dp = s0 * wd0 + s1 * wd1 + s2 * wd2 + s3 * wd3;
        #pragma unroll
        for (int o = 16; o; o >>= 1) {
            th += __shfl_xor_sync(0xffffffffu, th, o);
            dp += __shfl_xor_sync(0xffffffffu, dp, o);
        }
        float theta = (th + bth) * 3.0f;
        int q = q_data[n];
        float alpha = softplusf_(dp + g_qdtab[q] + bd);
        float be0 = g_betatab[q * 3 + 0];
        float be1 = g_betatab[q * 3 + 1];
        float be2 = g_betatab[q * 3 + 2];
        float feat[5] = {theta, alpha, be0, be1, be2};

        float h1a = sBc1[lane], h1b = sBc1[lane + 32];
        #pragma unroll
        for (int i = 0; i < 5; i++) {
            h1a = fmaf(feat[i], sWc1[i * 64 + lane], h1a);
            h1b = fmaf(feat[i], sWc1[i * 64 + lane + 32], h1b);
        }
        h1s[warp][lane] = fmaxf(h1a, 0.0f);
        h1s[warp][lane + 32] = fmaxf(h1b, 0.0f);
        __syncwarp();
        float h2 = sBc2[lane];
        #pragma unroll
        for (int i = 0; i < 64; i++) h2 = fmaf(h1s[warp][i], sWc2[i * 32 + lane], h2);
        h2 = fmaxf(h2, 0.0f);
        float lg = h2 * cw;
        #pragma unroll
        for (int o = 16; o; o >>= 1) lg += __shfl_xor_sync(0xffffffffu, lg, o);

        if (lane == 0) {
            float l0 = lg + cb0, l1 = lg + cb1, l2 = lg + cb2;
            float c1 = sigmoidf_(l0);
            float c2 = c1 * sigmoidf_(l1);
            float c3 = c2 * sigmoidf_(l2);
            const size_t N = NT;
            out[n] = theta;
            out[N + n * 3 + 0] = be0;
            out[N + n * 3 + 1] = be1;
            out[N + n * 3 + 2] = be2;
            out[4 * N + n] = alpha;
            out[5 * N + n * 4 + 0] = 1.0f - c1;
            out[5 * N + n * 4 + 1] = c1 - c2;
            out[5 * N + n * 4 + 2] = c2 - c3;
            out[5 * N + n * 4 + 3] = c3;
            out[9 * N + n * 3 + 0] = l0;
            out[9 * N + n * 3 + 1] = l1;
            out[9 * N + n * 3 + 2] = l2;
        }
        __syncwarp();
    }
}

// ---------------- launch -----------------------------------------------------
extern "C" void kernel_launch(void* const* d_in, const int* in_sizes, int n_in,
                              void* d_out, int out_size) {
    const int*   q_data   = (const int*)d_in[0];
    const int*   r_data   = (const int*)d_in[1];
    const float* qe_table = (const float*)d_in[2];
    const float* key_mem  = (const float*)d_in[3];
    const float* initMv   = (const float*)d_in[4];
    const float* W_value  = (const float*)d_in[5];
    const float* b_value  = (const float*)d_in[6];
    const float* W_erase  = (const float*)d_in[7];
    const float* b_erase  = (const float*)d_in[8];
    const float* W_add    = (const float*)d_in[9];
    const float* b_add    = (const float*)d_in[10];
    const float* W_summary= (const float*)d_in[11];
    const float* b_summary= (const float*)d_in[12];
    const float* W_theta  = (const float*)d_in[13];
    const float* b_theta  = (const float*)d_in[14];
    const float* W_beta   = (const float*)d_in[15];
    const float* b_beta   = (const float*)d_in[16];
    const float* W_disc   = (const float*)d_in[17];
    const float* b_disc   = (const float*)d_in[18];
    const float* W_c1     = (const float*)d_in[19];
    const float* b_c1     = (const float*)d_in[20];
    const float* W_c2     = (const float*)d_in[21];
    const float* b_c2     = (const float*)d_in[22];
    const float* coral_w  = (const float*)d_in[23];
    const float* coral_b  = (const float*)d_in[24];
    float* out = (float*)d_out;

    // L1: wtab + perq + bv/EA0
    wtab_perq_kernel<<<QMAX + 1, 128>>>(qe_table, key_mem, b_value, W_erase, W_add,
                                        b_erase, b_add, W_summary, b_summary,
                                        W_beta, b_beta, W_disc);
    // L2: fused PP GEMM + EA table
    {
        dim3 g(4, 79);
        ppea_kernel<<<g, 256>>>(W_value, W_erase, W_add);
    }
    // L3: scan
    scan_kernel<<<BB, 512>>>(q_data, r_data, initMv);
    // L4: summary GEMM (<- ncu capture slot)
    sgemm_sum_kernel<<<NT / 128, 256>>>(q_data, W_summary);
    // L5: head
    head_kernel<<<NT / (8 * 32), 256>>>(q_data, W_theta, b_theta, W_disc, b_disc,
                                        W_c1, b_c1, W_c2, b_c2, coral_w, coral_b, out);
}

// round 13
// speedup vs baseline: 1.4065x; 1.2419x over previous
#include <cuda_runtime.h>
#include <math.h>

// Problem dims
#define BB 128
#define SS 1024
#define QMAX 5001          // q ids 0..5000
#define MSLOT 64
#define KDIM 128
#define VDIM 256
#define FDIM 128
#define NT 131072          // BB*SS

typedef unsigned long long ull;

// ---------------- scratch (static device arrays: no allocation) -------------
__device__ float g_Wtab[QMAX * MSLOT];          // softmax(qe @ K^T) per q
__device__ float g_bvE2[512];                   // b_value@[We|Wa] + [b_erase|b_add]
__device__ float g_EAtab[QMAX * 4 * 512];       // [q][r][ erase(256) | add(256) ]
__device__ float g_QStab[QMAX * FDIM];          // qe @ W_summary[256:384] + b_summary
__device__ float g_betatab[QMAX * 3];           // qe @ W_beta + b_beta
__device__ float g_qdtab[QMAX];                 // qe @ W_disc[128:256]
__device__ float g_read[(size_t)NT * VDIM];     // per-step memory reads
__device__ float g_summary[(size_t)NT * FDIM];  // tanh summary

// ---------------- packed f32x2 helpers --------------------------------------
__device__ __forceinline__ ull pack2(float lo, float hi) {
    ull d; asm("mov.b64 %0, {%1, %2};" : "=l"(d) : "f"(lo), "f"(hi)); return d;
}
__device__ __forceinline__ void unpack2(ull v, float& lo, float& hi) {
    asm("mov.b64 {%0, %1}, %2;" : "=f"(lo), "=f"(hi) : "l"(v));
}
__device__ __forceinline__ ull fma2(ull a, ull b, ull c) {
    ull d; asm("fma.rn.f32x2 %0, %1, %2, %3;" : "=l"(d) : "l"(a), "l"(b), "l"(c));
    return d;
}

__device__ __forceinline__ float sigmoidf_(float x) { return 1.0f / (1.0f + expf(-x)); }
__device__ __forceinline__ float softplusf_(float x) {
    return fmaxf(x, 0.0f) + log1pf(expf(-fabsf(x)));
}

// ---------------- K1: fused wtab + perq (per q) ------------------------------
__global__ void __launch_bounds__(128) wtab_perq_kernel(const float* __restrict__ qe_table,
                                                        const float* __restrict__ key_memory,
                                                        const float* __restrict__ W_summary,
                                                        const float* __restrict__ b_summary,
                                                        const float* __restrict__ W_beta,
                                                        const float* __restrict__ b_beta,
                                                        const float* __restrict__ W_disc) {
    int t = threadIdx.x;
    int q = blockIdx.x;
    __shared__ float qe[KDIM];
    __shared__ float sh_d[MSLOT];
    __shared__ float sh_e[MSLOT];
    qe[t] = qe_table[q * KDIM + t];
    __syncthreads();
    float d = 0.0f;
    if (t < MSLOT) {
        #pragma unroll 8
        for (int k = 0; k < KDIM; k++) d = fmaf(qe[k], key_memory[t * KDIM + k], d);
        sh_d[t] = d;
    }
    __syncthreads();
    if (t < MSLOT) {
        float mx = -1e30f;
        #pragma unroll 8
        for (int i = 0; i < MSLOT; i++) mx = fmaxf(mx, sh_d[i]);
        sh_e[t] = expf(d - mx);
    }
    __syncthreads();
    if (t < MSLOT) {
        float sum = 0.0f;
        #pragma unroll 8
        for (int i = 0; i < MSLOT; i++) sum += sh_e[i];
        g_Wtab[q * MSLOT + t] = sh_e[t] / sum;
    }
    // perq projections
    {
        float acc = b_summary[t];
        #pragma unroll 8
        for (int dd = 0; dd < KDIM; dd++)
            acc = fmaf(qe[dd], W_summary[(256 + dd) * FDIM + t], acc);
        g_QStab[q * FDIM + t] = acc;
    }
    if (t < 3) {
        float a = b_beta[t];
        for (int dd = 0; dd < KDIM; dd++) a = fmaf(qe[dd], W_beta[dd * 3 + t], a);
        g_betatab[q * 3 + t] = a;
    } else if (t == 4) {
        float a = 0.0f;
        for (int dd = 0; dd < KDIM; dd++) a = fmaf(qe[dd], W_disc[128 + dd], a);
        g_qdtab[q] = a;
    }
}

// ---------------- K1b (tiny): bv bias row + EAtab[q=0] -----------------------
__global__ void __launch_bounds__(128) bv_ea0_kernel(const float* __restrict__ b_value,
                                                     const float* __restrict__ W_erase,
                                                     const float* __restrict__ W_add,
                                                     const float* __restrict__ b_erase,
                                                     const float* __restrict__ b_add) {
    int t = threadIdx.x;
    for (int j = t; j < 512; j += 128) {
        const float* W = (j < 256) ? (W_erase + j) : (W_add + (j - 256));
        float a = 0.0f;
        for (int k = 0; k < 256; k++) a = fmaf(b_value[k], W[k * 256], a);
        float bias = (j < 256) ? b_erase[j] : b_add[j - 256];
        float x = a + bias;
        g_bvE2[j] = x;
        float act = (j < 256) ? sigmoidf_(x) : tanhf(x);
        #pragma unroll
        for (int rr = 0; rr < 4; rr++) g_EAtab[(size_t)rr * 512 + j] = act;
    }
}

// ---------------- K2: fused PP-GEMM + EA table -------------------------------
// C1[q,:] = Wv[q]·[We|Wa], C2[q,:] = Wv[5000+q]·[We|Wa]  (q = q_id-1, 0..4999)
// EA[q+1][r][col] = act( C1 + bvE2 + (r/3)·C2 )
__global__ void __launch_bounds__(256, 2) ppea_kernel(const float* __restrict__ Wv,
                                                      const float* __restrict__ We,
                                                      const float* __restrict__ Wa) {
    const int K = 256;
    __shared__ float As1[8][128];  // duplicated pairs: 64 rows
    __shared__ float As2[8][128];
    __shared__ float Bs[8][128];
    int tid = threadIdx.x;
    int row0 = blockIdx.y * 64, col0 = blockIdx.x * 128;
    int lrow = (tid & 127) >> 1, ak4 = (tid & 1) * 4;
    int bK = tid >> 5, bCol = (tid & 31) * 4;
    int tx = tid & 15, ty = tid >> 4;
    ull acc1[4][4], acc2[4][4];
    #pragma unroll
    for (int i = 0; i < 4; i++)
        #pragma unroll
        for (int j = 0; j < 4; j++) { acc1[i][j] = 0ull; acc2[i][j] = 0ull; }

    int gr = row0 + lrow;
    bool valid = (gr < 5000);
    const float* aptr = Wv + ((tid < 128) ? (size_t)gr * K : (size_t)(5000 + gr) * K);
    for (int k0 = 0; k0 < K; k0 += 8) {
        float4 av = make_float4(0, 0, 0, 0);
        if (valid) av = __ldg((const float4*)(aptr + k0 + ak4));
        float (*As)[128] = (tid < 128) ? As1 : As2;
        *(float2*)&As[ak4 + 0][2 * lrow] = make_float2(av.x, av.x);
        *(float2*)&As[ak4 + 1][2 * lrow] = make_float2(av.y, av.y);
        *(float2*)&As[ak4 + 2][2 * lrow] = make_float2(av.z, av.z);
        *(float2*)&As[ak4 + 3][2 * lrow] = make_float2(av.w, av.w);
        int j = col0 + bCol;
        const float* bp = (j < 256) ? (We + (k0 + bK) * 256 + j)
                                    : (Wa + (k0 + bK) * 256 + (j - 256));
        *(float4*)&Bs[bK][bCol] = __ldg((const float4*)bp);
        __syncthreads();
        #pragma unroll
        for (int kk = 0; kk < 8; kk++) {
            ull ra1[4], ra2[4], rb[4];
            #pragma unroll
            for (int i = 0; i < 4; i++) {
                ra1[i] = *(const ull*)&As1[kk][2 * (ty * 4 + i)];
                ra2[i] = *(const ull*)&As2[kk][2 * (ty * 4 + i)];
            }
            #pragma unroll
            for (int jp = 0; jp < 4; jp++) rb[jp] = *(const ull*)&Bs[kk][jp * 32 + tx * 2];
            #pragma unroll
            for (int i = 0; i < 4; i++)
                #pragma unroll
                for (int jp = 0; jp < 4; jp++) {
                    acc1[i][jp] = fma2(ra1[i], rb[jp], acc1[i][jp]);
                    acc2[i][jp] = fma2(ra2[i], rb[jp], acc2[i][jp]);
                }
        }
        __syncthreads();
    }
    bool is_erase = (col0 < 256);
    #pragma unroll
    for (int i = 0; i < 4; i++) {
        int row = ty * 4 + i;
        int q = row0 + row;            // q_id - 1
        if (q >= 5000) continue;
        #pragma unroll
        for (int jp = 0; jp < 4; jp++) {
            int c = col0 + jp * 32 + tx * 2;
            float c1lo, c1hi, c2lo, c2hi;
            unpack2(acc1[i][jp], c1lo, c1hi);
            unpack2(acc2[i][jp], c2lo, c2hi);
            float blo = g_bvE2[c], bhi = g_bvE2[c + 1];
            float x1lo = c1lo + blo, x1hi = c1hi + bhi;
            #pragma unroll
            for (int rr = 0; rr < 4; rr++) {
                float sc = (float)rr * (1.0f / 3.0f);
                float xlo = fmaf(sc, c2lo, x1lo);
                float xhi = fmaf(sc, c2hi, x1hi);
                float olo = is_erase ? sigmoidf_(xlo) : tanhf(xlo);
                float ohi = is_erase ? sigmoidf_(xhi) : tanhf(xhi);
                *(float2*)&g_EAtab[((size_t)(q + 1) * 4 + rr) * 512 + c] = make_float2(olo, ohi);
            }
        }
    }
}

// ---------------- K3: scan, v-split across 2 CTAs per batch ------------------
// grid = 256: b = blk>>1, v-half = (blk&1)*128. 512 threads:
// quarter = tid&3 -> m range quarter*16..+16 ; pv = tid>>2 -> v = vh + pv.
// Thread owns 1 v x 16 m. R[i] = (Mv[m0+2i, v], Mv[m0+2i+1, v]) packed over m.
// w pairs load directly from smem ring as ull (natural contiguous pairing).
__device__ __forceinline__ void ea_pref2(int qr, int v, float& e, float& a) {
    const float* ea = g_EAtab + (size_t)qr * 512;
    e = __ldg(ea + v);
    a = __ldg(ea + 256 + v);
}

__device__ __forceinline__ void scan_step2(ull* R, const float* wrow,
                                           float e, float a, int quarter, float* outp) {
    ull ne = pack2(-e, -e), aa = pack2(a, a);
    const ulonglong2* wp = (const ulonglong2*)wrow;
    ulonglong2 w01 = wp[0], w23 = wp[1], w45 = wp[2], w67 = wp[3];
    ull W[8] = {w01.x, w01.y, w23.x, w23.y, w45.x, w45.y, w67.x, w67.y};
    ull acca = 0ull, accb = 0ull;
    #pragma unroll
    for (int i = 0; i < 4; i++) {
        ull t = fma2(ne, R[i], aa);          // a - e*Mv  (both m of pair)
        acca = fma2(W[i], R[i], acca);       // read partial
        R[i] = fma2(W[i], t, R[i]);          // Mv += w*(a - e*Mv)
    }
    #pragma unroll
    for (int i = 4; i < 8; i++) {
        ull t = fma2(ne, R[i], aa);
        accb = fma2(W[i], R[i], accb);
        R[i] = fma2(W[i], t, R[i]);
    }
    float lo0, hi0, lo1, hi1;
    unpack2(acca, lo0, hi0);
    unpack2(accb, lo1, hi1);
    float rd = (lo0 + lo1) + (hi0 + hi1);            // sum over this quarter's 16 m
    rd += __shfl_xor_sync(0xffffffffu, rd, 1);       // combine 4 quarters
    rd += __shfl_xor_sync(0xffffffffu, rd, 2);
    if (quarter == 0) *outp = rd;
}

__global__ void __launch_bounds__(512, 2) scan_kernel(const int* __restrict__ q_data,
                                                      const int* __restrict__ r_data,
                                                      const float* __restrict__ initMv) {
    const int blk = blockIdx.x;
    const int b = blk >> 1;
    const int vh = (blk & 1) << 7;     // 0 or 128
    const int tid = threadIdx.x;
    const int quarter = tid & 3;
    const int pv = tid >> 2;
    const int v = vh + pv;
    const int m0 = quarter * 16;

    __shared__ int qr_sh[SS + 8];
    __shared__ float wring[64 * MSLOT];   // 64 steps x 64 floats = 16KB

    for (int i = tid; i < SS; i += 512)
        qr_sh[i] = q_data[b * SS + i] * 4 + r_data[b * SS + i];
    if (tid < 8)
        qr_sh[SS + tid] = q_data[b * SS + SS - 1] * 4 + r_data[b * SS + SS - 1];

    ull R[8];
    #pragma unroll
    for (int i = 0; i < 8; i++)
        R[i] = pack2(initMv[(m0 + 2 * i) * VDIM + v], initMv[(m0 + 2 * i + 1) * VDIM + v]);
    __syncthreads();

    float eA, aA, eB, aB, eC, aC, eD, aD;
    ea_pref2(qr_sh[0], v, eA, aA);
    ea_pref2(qr_sh[1], v, eB, aB);
    ea_pref2(qr_sh[2], v, eC, aC);

    float* rdbase = g_read + ((size_t)b << 10) * VDIM + v;

    #pragma unroll 1
    for (int c = 0; c < 16; c++) {
        __syncthreads();   // prior chunk fully consumed before ring overwrite
        {   // cooperative refill: 64 steps x 64 floats, 2 float4 per thread
            int u = tid * 2;
            int sl = u >> 4;
            int fi = u & 15;
            const float* src = g_Wtab + (qr_sh[c * 64 + sl] >> 2) * MSLOT;
            *(float4*)&wring[sl * MSLOT + fi * 4]       = __ldg((const float4*)(src + fi * 4));
            *(float4*)&wring[sl * MSLOT + (fi + 1) * 4] = __ldg((const float4*)(src + (fi + 1) * 4));
        }
        __syncthreads();
        int base = c * 64;
        #pragma unroll 1
        for (int k = 0; k < 16; k++) {
            int s = base + k * 4;
            ea_pref2(qr_sh[s + 3], v, eD, aD);
            scan_step2(R, &wring[((s) & 63) * MSLOT + m0], eA, aA, quarter,
                       rdbase + (size_t)s * VDIM);
            ea_pref2(qr_sh[s + 4], v, eA, aA);
            scan_step2(R, &wring[((s + 1) & 63) * MSLOT + m0], eB, aB, quarter,
                       rdbase + (size_t)(s + 1) * VDIM);
            ea_pref2(qr_sh[s + 5], v, eB, aB);
            scan_step2(R, &wring[((s + 2) & 63) * MSLOT + m0], eC, aC, quarter,
                       rdbase + (size_t)(s + 2) * VDIM);
            ea_pref2(qr_sh[s + 6], v, eC, aC);
            scan_step2(R, &wring[((s + 3) & 63) * MSLOT + m0], eD, aD, quarter,
                       rdbase + (size_t)(s + 3) * VDIM);
        }
    }
}

// ---------------- K4: summary SGEMM (131072x256 @ 256x128), f32x2, tanh ------
__global__ void __launch_bounds__(256) sgemm_sum_kernel(const int* __restrict__ q_data,
                                                        const float* __restrict__ W_summary) {
    const int K = 256, N = 128;
    __shared__ float As[8][256];   // duplicated
    __shared__ float Bs[8][128];
    __shared__ int qrow_s[128];
    int tid = threadIdx.x;
    int row0 = blockIdx.x * 128;
    if (tid < 128) qrow_s[tid] = q_data[row0 + tid];
    int aRow = tid >> 1, aK4 = (tid & 1) * 4;
    int bK = tid >> 5, bCol = (tid & 31) * 4;
    int tx = tid & 15, ty = tid >> 4;
    ull acc2[8][4];
    #pragma unroll
    for (int i = 0; i < 8; i++)
        #pragma unroll
        for (int j = 0; j < 4; j++) acc2[i][j] = 0ull;

    const float* A = g_read;
    for (int k0 = 0; k0 < K; k0 += 8) {
        float4 av = __ldg((const float4*)(A + (size_t)(row0 + aRow) * K + k0 + aK4));
        *(float2*)&As[aK4 + 0][2 * aRow] = make_float2(av.x, av.x);
        *(float2*)&As[aK4 + 1][2 * aRow] = make_float2(av.y, av.y);
        *(float2*)&As[aK4 + 2][2 * aRow] = make_float2(av.z, av.z);
        *(float2*)&As[aK4 + 3][2 * aRow] = make_float2(av.w, av.w);
        *(float4*)&Bs[bK][bCol] = __ldg((const float4*)(W_summary + (k0 + bK) * N + bCol));
        __syncthreads();
        #pragma unroll
        for (int kk = 0; kk < 8; kk++) {
            ull ra[8], rb[4];
            #pragma unroll
            for (int i = 0; i < 8; i++) ra[i] = *(const ull*)&As[kk][2 * (ty * 8 + i)];
            #pragma unroll
            for (int jp = 0; jp < 4; jp++) rb[jp] = *(const ull*)&Bs[kk][jp * 32 + tx * 2];
            #pragma unroll
            for (int i = 0; i < 8; i++)
                #pragma unroll
                for (int jp = 0; jp < 4; jp++)
                    acc2[i][jp] = fma2(ra[i], rb[jp], acc2[i][jp]);
        }
        __syncthreads();
    }
    #pragma unroll
    for (int i = 0; i < 8; i++) {
        int rl = ty * 8 + i;
        int r = row0 + rl;
        int q = qrow_s[rl];
        const float* qs = g_QStab + q * FDIM;
        #pragma unroll
        for (int jp = 0; jp < 4; jp++) {
            int c = jp * 32 + tx * 2;
            float lo, hi; unpack2(acc2[i][jp], lo, hi);
            *(float2*)&g_summary[(size_t)r * N + c] =
                make_float2(tanhf(lo + __ldg(qs + c)), tanhf(hi + __ldg(qs + c + 1)));
        }
    }
}

// ---------------- K5: per-token head (theta/alpha/CORAL), 32 tokens/warp -----
__global__ void __launch_bounds__(256) head_kernel(const int* __restrict__ q_data,
                                                   const float* __restrict__ W_theta,
                                                   const float* __restrict__ b_theta,
                                                   const float* __restrict__ W_disc,
                                                   const float* __restrict__ b_disc,
                                                   const float* __restrict__ W_c1,
                                                   const float* __restrict__ b_c1,
                                                   const float* __restrict__ W_c2,
                                                   const float* __restrict__ b_c2,
                                                   const float* __restrict__ coral_w,
                                                   const float* __restrict__ coral_b,
                                                   float* __restrict__ out) {
    __shared__ float sWc1[5 * 64], sBc1[64], sWc2[64 * 32], sBc2[32], sCw[32];
    __shared__ float sWth[128], sWd[128];
    __shared__ float h1s[8][64];
    int tid = threadIdx.x;
    for (int i = tid; i < 320; i += 256) sWc1[i] = W_c1[i];
    for (int i = tid; i < 2048; i += 256) sWc2[i] = W_c2[i];
    if (tid < 64) sBc1[tid] = b_c1[tid];
    if (tid < 32) { sBc2[tid] = b_c2[tid]; sCw[tid] = coral_w[tid]; }
    if (tid < 128) { sWth[tid] = W_theta[tid]; sWd[tid] = W_disc[tid]; }
    __syncthreads();

    int warp = tid >> 5, lane = tid & 31;
    float bth = b_theta[0], bd = b_disc[0];
    float cb0 = coral_b[0], cb1 = coral_b[1], cb2 = coral_b[2];
    float wth0 = sWth[lane], wth1 = sWth[lane + 32], wth2 = sWth[lane + 64], wth3 = sWth[lane + 96];
    float wd0 = sWd[lane], wd1 = sWd[lane + 32], wd2 = sWd[lane + 64], wd3 = sWd[lane + 96];
    float cw = sCw[lane];

    const int TOK = 32;
    size_t base = ((size_t)blockIdx.x * 8 + warp) * TOK;
    for (int t = 0; t < TOK; t++) {
        size_t n = base + t;
        const float* srow = g_summary + n * FDIM;
        float s0 = __ldg(srow + lane), s1 = __ldg(srow + lane + 32);
        float s2 = __ldg(srow + lane + 64), s3 = __ldg(srow + lane + 96);
        float th = s0 * wth0 + s1 * wth1 + s2 * wth2 + s3 * wth3;
        float dp = s0 * wd0 + s1 * wd1 + s2 * wd2 + s3 * wd3;
        #pragma unroll
        for (int o = 16; o; o >>= 1) {
            th += __shfl_xor_sync(0xffffffffu, th, o);
            dp += __shfl_xor_sync(0xffffffffu, dp, o);
        }
        float theta = (th + bth) * 3.0f;
        int q = q_data[n];
        float alpha = softplusf_(dp + g_qdtab[q] + bd);
        float be0 = g_betatab[q * 3 + 0];
        float be1 = g_betatab[q * 3 + 1];
        float be2 = g_betatab[q * 3 + 2];
        float feat[5] = {theta, alpha, be0, be1, be2};

        float h1a = sBc1[lane], h1b = sBc1[lane + 32];
        #pragma unroll
        for (int i = 0; i < 5; i++) {
            h1a = fmaf(feat[i], sWc1[i * 64 + lane], h1a);
            h1b = fmaf(feat[i], sWc1[i * 64 + lane + 32], h1b);
        }
        h1s[warp][lane] = fmaxf(h1a, 0.0f);
        h1s[warp][lane + 32] = fmaxf(h1b, 0.0f);
        __syncwarp();
        float h2 = sBc2[lane];
        #pragma unroll
        for (int i = 0; i < 64; i++) h2 = fmaf(h1s[warp][i], sWc2[i * 32 + lane], h2);
        h2 = fmaxf(h2, 0.0f);
        float lg = h2 * cw;
        #pragma unroll
        for (int o = 16; o; o >>= 1) lg += __shfl_xor_sync(0xffffffffu, lg, o);

        if (lane == 0) {
            float l0 = lg + cb0, l1 = lg + cb1, l2 = lg + cb2;
            float c1 = sigmoidf_(l0);
            float c2 = c1 * sigmoidf_(l1);
            float c3 = c2 * sigmoidf_(l2);
            const size_t N = NT;
            out[n] = theta;
            out[N + n * 3 + 0] = be0;
            out[N + n * 3 + 1] = be1;
            out[N + n * 3 + 2] = be2;
            out[4 * N + n] = alpha;
            out[5 * N + n * 4 + 0] = 1.0f - c1;
            out[5 * N + n * 4 + 1] = c1 - c2;
            out[5 * N + n * 4 + 2] = c2 - c3;
            out[5 * N + n * 4 + 3] = c3;
            out[9 * N + n * 3 + 0] = l0;
            out[9 * N + n * 3 + 1] = l1;
            out[9 * N + n * 3 + 2] = l2;
        }
        __syncwarp();
    }
}

// ---------------- launch -----------------------------------------------------
extern "C" void kernel_launch(void* const* d_in, const int* in_sizes, int n_in,
                              void* d_out, int out_size) {
    const int*   q_data   = (const int*)d_in[0];
    const int*   r_data   = (const int*)d_in[1];
    const float* qe_table = (const float*)d_in[2];
    const float* key_mem  = (const float*)d_in[3];
    const float* initMv   = (const float*)d_in[4];
    const float* W_value  = (const float*)d_in[5];
    const float* b_value  = (const float*)d_in[6];
    const float* W_erase  = (const float*)d_in[7];
    const float* b_erase  = (const float*)d_in[8];
    const float* W_add    = (const float*)d_in[9];
    const float* b_add    = (const float*)d_in[10];
    const float* W_summary= (const float*)d_in[11];
    const float* b_summary= (const float*)d_in[12];
    const float* W_theta  = (const float*)d_in[13];
    const float* b_theta  = (const float*)d_in[14];
    const float* W_beta   = (const float*)d_in[15];
    const float* b_beta   = (const float*)d_in[16];
    const float* W_disc   = (const float*)d_in[17];
    const float* b_disc   = (const float*)d_in[18];
    const float* W_c1     = (const float*)d_in[19];
    const float* b_c1     = (const float*)d_in[20];
    const float* W_c2     = (const float*)d_in[21];
    const float* b_c2     = (const float*)d_in[22];
    const float* coral_w  = (const float*)d_in[23];
    const float* coral_b  = (const float*)d_in[24];
    float* out = (float*)d_out;

    // L1: wtab + perq
    wtab_perq_kernel<<<QMAX, 128>>>(qe_table, key_mem, W_summary, b_summary,
                                    W_beta, b_beta, W_disc);
    // L2 (tiny): bv bias + EA row 0
    bv_ea0_kernel<<<1, 128>>>(b_value, W_erase, W_add, b_erase, b_add);
    // L3: fused PP GEMM + EA table
    {
        dim3 g(4, 79);
        ppea_kernel<<<g, 256>>>(W_value, W_erase, W_add);
    }
    // L4: scan, v-split (<- ncu capture slot)
    scan_kernel<<<BB * 2, 512>>>(q_data, r_data, initMv);
    // L5: summary GEMM
    sgemm_sum_kernel<<<NT / 128, 256>>>(q_data, W_summary);
    // L6: head
    head_kernel<<<NT / (8 * 32), 256>>>(q_data, W_theta, b_theta, W_disc, b_disc,
                                        W_c1, b_c1, W_c2, b_c2, coral_w, coral_b, out);
}

// round 14
// speedup vs baseline: 1.6473x; 1.1712x over previous
#include <cuda_runtime.h>
#include <math.h>

// Problem dims
#define BB 128
#define SS 1024
#define QMAX 5001          // q ids 0..5000
#define MSLOT 64
#define KDIM 128
#define VDIM 256
#define FDIM 128
#define NT 131072          // BB*SS

typedef unsigned long long ull;

// ---------------- scratch (static device arrays: no allocation) -------------
__device__ float g_Wtab[QMAX * MSLOT];          // softmax(qe @ K^T) per q
__device__ float g_bvE2[512];                   // b_value@[We|Wa] + [b_erase|b_add]
__device__ float g_EAtab[QMAX * 4 * 512];       // [q][r][ erase(256) | add(256) ]
__device__ float g_QStab[QMAX * FDIM];          // qe @ W_summary[256:384] + b_summary
__device__ float g_betatab[QMAX * 3];           // qe @ W_beta + b_beta
__device__ float g_qdtab[QMAX];                 // qe @ W_disc[128:256]
__device__ float g_read[(size_t)NT * VDIM];     // per-step memory reads
__device__ float g_summary[(size_t)NT * FDIM];  // tanh summary

// ---------------- packed f32x2 helpers --------------------------------------
__device__ __forceinline__ ull pack2(float lo, float hi) {
    ull d; asm("mov.b64 %0, {%1, %2};" : "=l"(d) : "f"(lo), "f"(hi)); return d;
}
__device__ __forceinline__ void unpack2(ull v, float& lo, float& hi) {
    asm("mov.b64 {%0, %1}, %2;" : "=f"(lo), "=f"(hi) : "l"(v));
}
__device__ __forceinline__ ull fma2(ull a, ull b, ull c) {
    ull d; asm("fma.rn.f32x2 %0, %1, %2, %3;" : "=l"(d) : "l"(a), "l"(b), "l"(c));
    return d;
}

__device__ __forceinline__ float sigmoidf_(float x) { return 1.0f / (1.0f + expf(-x)); }
__device__ __forceinline__ float softplusf_(float x) {
    return fmaxf(x, 0.0f) + log1pf(expf(-fabsf(x)));
}

// ---------------- K1: fused wtab + perq (per q) ------------------------------
__global__ void __launch_bounds__(128) wtab_perq_kernel(const float* __restrict__ qe_table,
                                                        const float* __restrict__ key_memory,
                                                        const float* __restrict__ W_summary,
                                                        const float* __restrict__ b_summary,
                                                        const float* __restrict__ W_beta,
                                                        const float* __restrict__ b_beta,
                                                        const float* __restrict__ W_disc) {
    int t = threadIdx.x;
    int q = blockIdx.x;
    __shared__ float qe[KDIM];
    __shared__ float sh_d[MSLOT];
    __shared__ float sh_e[MSLOT];
    qe[t] = qe_table[q * KDIM + t];
    __syncthreads();
    float d = 0.0f;
    if (t < MSLOT) {
        #pragma unroll 8
        for (int k = 0; k < KDIM; k++) d = fmaf(qe[k], key_memory[t * KDIM + k], d);
        sh_d[t] = d;
    }
    __syncthreads();
    if (t < MSLOT) {
        float mx = -1e30f;
        #pragma unroll 8
        for (int i = 0; i < MSLOT; i++) mx = fmaxf(mx, sh_d[i]);
        sh_e[t] = expf(d - mx);
    }
    __syncthreads();
    if (t < MSLOT) {
        float sum = 0.0f;
        #pragma unroll 8
        for (int i = 0; i < MSLOT; i++) sum += sh_e[i];
        g_Wtab[q * MSLOT + t] = sh_e[t] / sum;
    }
    // perq projections
    {
        float acc = b_summary[t];
        #pragma unroll 8
        for (int dd = 0; dd < KDIM; dd++)
            acc = fmaf(qe[dd], W_summary[(256 + dd) * FDIM + t], acc);
        g_QStab[q * FDIM + t] = acc;
    }
    if (t < 3) {
        float a = b_beta[t];
        for (int dd = 0; dd < KDIM; dd++) a = fmaf(qe[dd], W_beta[dd * 3 + t], a);
        g_betatab[q * 3 + t] = a;
    } else if (t == 4) {
        float a = 0.0f;
        for (int dd = 0; dd < KDIM; dd++) a = fmaf(qe[dd], W_disc[128 + dd], a);
        g_qdtab[q] = a;
    }
}

// ---------------- K1b (tiny): bv bias row + EAtab[q=0] -----------------------
__global__ void __launch_bounds__(128) bv_ea0_kernel(const float* __restrict__ b_value,
                                                     const float* __restrict__ W_erase,
                                                     const float* __restrict__ W_add,
                                                     const float* __restrict__ b_erase,
                                                     const float* __restrict__ b_add) {
    int t = threadIdx.x;
    for (int j = t; j < 512; j += 128) {
        const float* W = (j < 256) ? (W_erase + j) : (W_add + (j - 256));
        float a = 0.0f;
        for (int k = 0; k < 256; k++) a = fmaf(b_value[k], W[k * 256], a);
        float bias = (j < 256) ? b_erase[j] : b_add[j - 256];
        float x = a + bias;
        g_bvE2[j] = x;
        float act = (j < 256) ? sigmoidf_(x) : tanhf(x);
        #pragma unroll
        for (int rr = 0; rr < 4; rr++) g_EAtab[(size_t)rr * 512 + j] = act;
    }
}

// ---------------- K2: fused PP-GEMM + EA table -------------------------------
// C1[q,:] = Wv[q]·[We|Wa], C2[q,:] = Wv[5000+q]·[We|Wa]  (q = q_id-1, 0..4999)
// EA[q+1][r][col] = act( C1 + bvE2 + (r/3)·C2 )
__global__ void __launch_bounds__(256, 2) ppea_kernel(const float* __restrict__ Wv,
                                                      const float* __restrict__ We,
                                                      const float* __restrict__ Wa) {
    const int K = 256;
    __shared__ float As1[8][128];  // duplicated pairs: 64 rows
    __shared__ float As2[8][128];
    __shared__ float Bs[8][128];
    int tid = threadIdx.x;
    int row0 = blockIdx.y * 64, col0 = blockIdx.x * 128;
    int lrow = (tid & 127) >> 1, ak4 = (tid & 1) * 4;
    int bK = tid >> 5, bCol = (tid & 31) * 4;
    int tx = tid & 15, ty = tid >> 4;
    ull acc1[4][4], acc2[4][4];
    #pragma unroll
    for (int i = 0; i < 4; i++)
        #pragma unroll
        for (int j = 0; j < 4; j++) { acc1[i][j] = 0ull; acc2[i][j] = 0ull; }

    int gr = row0 + lrow;
    bool valid = (gr < 5000);
    const float* aptr = Wv + ((tid < 128) ? (size_t)gr * K : (size_t)(5000 + gr) * K);
    for (int k0 = 0; k0 < K; k0 += 8) {
        float4 av = make_float4(0, 0, 0, 0);
        if (valid) av = __ldg((const float4*)(aptr + k0 + ak4));
        float (*As)[128] = (tid < 128) ? As1 : As2;
        *(float2*)&As[ak4 + 0][2 * lrow] = make_float2(av.x, av.x);
        *(float2*)&As[ak4 + 1][2 * lrow] = make_float2(av.y, av.y);
        *(float2*)&As[ak4 + 2][2 * lrow] = make_float2(av.z, av.z);
        *(float2*)&As[ak4 + 3][2 * lrow] = make_float2(av.w, av.w);
        int j = col0 + bCol;
        const float* bp = (j < 256) ? (We + (k0 + bK) * 256 + j)
                                    : (Wa + (k0 + bK) * 256 + (j - 256));
        *(float4*)&Bs[bK][bCol] = __ldg((const float4*)bp);
        __syncthreads();
        #pragma unroll
        for (int kk = 0; kk < 8; kk++) {
            ull ra1[4], ra2[4], rb[4];
            #pragma unroll
            for (int i = 0; i < 4; i++) {
                ra1[i] = *(const ull*)&As1[kk][2 * (ty * 4 + i)];
                ra2[i] = *(const ull*)&As2[kk][2 * (ty * 4 + i)];
            }
            #pragma unroll
            for (int jp = 0; jp < 4; jp++) rb[jp] = *(const ull*)&Bs[kk][jp * 32 + tx * 2];
            #pragma unroll
            for (int i = 0; i < 4; i++)
                #pragma unroll
                for (int jp = 0; jp < 4; jp++) {
                    acc1[i][jp] = fma2(ra1[i], rb[jp], acc1[i][jp]);
                    acc2[i][jp] = fma2(ra2[i], rb[jp], acc2[i][jp]);
                }
        }
        __syncthreads();
    }
    bool is_erase = (col0 < 256);
    #pragma unroll
    for (int i = 0; i < 4; i++) {
        int row = ty * 4 + i;
        int q = row0 + row;            // q_id - 1
        if (q >= 5000) continue;
        #pragma unroll
        for (int jp = 0; jp < 4; jp++) {
            int c = col0 + jp * 32 + tx * 2;
            float c1lo, c1hi, c2lo, c2hi;
            unpack2(acc1[i][jp], c1lo, c1hi);
            unpack2(acc2[i][jp], c2lo, c2hi);
            float blo = g_bvE2[c], bhi = g_bvE2[c + 1];
            float x1lo = c1lo + blo, x1hi = c1hi + bhi;
            #pragma unroll
            for (int rr = 0; rr < 4; rr++) {
                float sc = (float)rr * (1.0f / 3.0f);
                float xlo = fmaf(sc, c2lo, x1lo);
                float xhi = fmaf(sc, c2hi, x1hi);
                float olo = is_erase ? sigmoidf_(xlo) : tanhf(xlo);
                float ohi = is_erase ? sigmoidf_(xhi) : tanhf(xhi);
                *(float2*)&g_EAtab[((size_t)(q + 1) * 4 + rr) * 512 + c] = make_float2(olo, ohi);
            }
        }
    }
}

// ---------------- K3: persistent recurrence scan (ring + W reg pipeline) -----
// 128 CTAs, 512 threads. Thread owns 2 v (2p, 2p+1) x 16 m (8 pairs).
// quarter = tid&3 (m range quarter*16..+16), p = tid>>2.
// W for step s+1 is LDS-prefetched into registers during step s (ping-pong).
__device__ __forceinline__ void ea_pref(int q, int r, int p, float2& ee, float2& aa) {
    const float* ea = g_EAtab + (size_t)(q * 4 + r) * 512;
    ee = __ldg((const float2*)(ea + 2 * p));
    aa = __ldg((const float2*)(ea + 256 + 2 * p));
}

__device__ __forceinline__ void ldW(ull* W, const float* src) {
    const ulonglong2* wp = (const ulonglong2*)src;
    ulonglong2 t0 = wp[0], t1 = wp[1], t2 = wp[2], t3 = wp[3];
    W[0] = t0.x; W[1] = t0.y; W[2] = t1.x; W[3] = t1.y;
    W[4] = t2.x; W[5] = t2.y; W[6] = t3.x; W[7] = t3.y;
}

__device__ __forceinline__ void scan_step(ull* R0, ull* R1, const ull* W,
                                          float2 ee, float2 aa,
                                          int quarter, float* outp) {
    ull ne0 = pack2(-ee.x, -ee.x), ne1 = pack2(-ee.y, -ee.y);
    ull a20 = pack2(aa.x, aa.x),   a21 = pack2(aa.y, aa.y);
    ull acc0a = 0ull, acc0b = 0ull, acc1a = 0ull, acc1b = 0ull;
    #pragma unroll
    for (int i = 0; i < 4; i++) {
        ull t0 = fma2(ne0, R0[i], a20);
        ull t1 = fma2(ne1, R1[i], a21);
        acc0a = fma2(W[i], R0[i], acc0a);
        acc1a = fma2(W[i], R1[i], acc1a);
        R0[i] = fma2(W[i], t0, R0[i]);
        R1[i] = fma2(W[i], t1, R1[i]);
    }
    #pragma unroll
    for (int i = 4; i < 8; i++) {
        ull t0 = fma2(ne0, R0[i], a20);
        ull t1 = fma2(ne1, R1[i], a21);
        acc0b = fma2(W[i], R0[i], acc0b);
        acc1b = fma2(W[i], R1[i], acc1b);
        R0[i] = fma2(W[i], t0, R0[i]);
        R1[i] = fma2(W[i], t1, R1[i]);
    }
    float x0a, y0a, x0b, y0b, x1a, y1a, x1b, y1b;
    unpack2(acc0a, x0a, y0a); unpack2(acc0b, x0b, y0b);
    unpack2(acc1a, x1a, y1a); unpack2(acc1b, x1b, y1b);
    float rd0 = (x0a + x0b) + (y0a + y0b);
    float rd1 = (x1a + x1b) + (y1a + y1b);
    rd0 += __shfl_xor_sync(0xffffffffu, rd0, 1);
    rd0 += __shfl_xor_sync(0xffffffffu, rd0, 2);
    rd1 += __shfl_xor_sync(0xffffffffu, rd1, 1);
    rd1 += __shfl_xor_sync(0xffffffffu, rd1, 2);
    if (quarter == 0) *(float2*)outp = make_float2(rd0, rd1);
}

__global__ void __launch_bounds__(512) scan_kernel(const int* __restrict__ q_data,
                                                   const int* __restrict__ r_data,
                                                   const float* __restrict__ initMv) {
    const int b = blockIdx.x;
    const int tid = threadIdx.x;
    const int quarter = tid & 3;
    const int p = tid >> 2;

    __shared__ int q_sh[SS + 8];
    __shared__ int r_sh[SS + 8];
    __shared__ float wring[64 * MSLOT];   // 64 steps x 64 floats = 16KB

    for (int i = tid; i < SS; i += 512) {
        q_sh[i] = q_data[b * SS + i];
        r_sh[i] = r_data[b * SS + i];
    }
    if (tid < 8) {
        q_sh[SS + tid] = q_data[b * SS + SS - 1];
        r_sh[SS + tid] = r_data[b * SS + SS - 1];
    }

    ull R0[8], R1[8];
    #pragma unroll
    for (int i = 0; i < 8; i++) {
        int m = quarter * 16 + 2 * i;
        R0[i] = pack2(initMv[m * VDIM + 2 * p],     initMv[(m + 1) * VDIM + 2 * p]);
        R1[i] = pack2(initMv[m * VDIM + 2 * p + 1], initMv[(m + 1) * VDIM + 2 * p + 1]);
    }
    __syncthreads();

    float2 eA, aA, eB, aB, eC, aC, eD, aD;
    ea_pref(q_sh[0], r_sh[0], p, eA, aA);
    ea_pref(q_sh[1], r_sh[1], p, eB, aB);
    ea_pref(q_sh[2], r_sh[2], p, eC, aC);

    float* rdbase = g_read + (((size_t)b << 10)) * VDIM + 2 * p;
    const int qoff = quarter * 16;

    ull W0[8], W1[8];

    #pragma unroll 1
    for (int c = 0; c < 16; c++) {
        __syncthreads();   // prior chunk fully consumed before ring overwrite
        {   // cooperative refill: 64 steps x 64 floats, 2 float4 per thread
            int u = tid * 2;
            int sl = u >> 4;
            int fi = u & 15;
            const float* src = g_Wtab + q_sh[c * 64 + sl] * MSLOT;
            *(float4*)&wring[sl * MSLOT + fi * 4]       = __ldg((const float4*)(src + fi * 4));
            *(float4*)&wring[sl * MSLOT + (fi + 1) * 4] = __ldg((const float4*)(src + (fi + 1) * 4));
        }
        __syncthreads();
        int base = c * 64;
        ldW(W0, &wring[qoff]);   // slot 0 of chunk
        #pragma unroll 1
        for (int k = 0; k < 16; k++) {
            int s = base + 4 * k;
            int sl = 4 * k;
            ldW(W1, &wring[(sl + 1) * MSLOT + qoff]);
            ea_pref(q_sh[s + 3], r_sh[s + 3], p, eD, aD);
            scan_step(R0, R1, W0, eA, aA, quarter, rdbase + (size_t)s * VDIM);

            ldW(W0, &wring[(sl + 2) * MSLOT + qoff]);
            ea_pref(q_sh[s + 4], r_sh[s + 4], p, eA, aA);
            scan_step(R0, R1, W1, eB, aB, quarter, rdbase + (size_t)(s + 1) * VDIM);

            ldW(W1, &wring[(sl + 3) * MSLOT + qoff]);
            ea_pref(q_sh[s + 5], r_sh[s + 5], p, eB, aB);
            scan_step(R0, R1, W0, eC, aC, quarter, rdbase + (size_t)(s + 2) * VDIM);

            ldW(W0, &wring[((sl + 4) & 63) * MSLOT + qoff]);  // wraps harmlessly at chunk end
            ea_pref(q_sh[s + 6], r_sh[s + 6], p, eC, aC);
            scan_step(R0, R1, W1, eD, aD, quarter, rdbase + (size_t)(s + 3) * VDIM);
        }
    }
}

// ---------------- K4: summary SGEMM (131072x256 @ 256x128), f32x2, tanh ------
__global__ void __launch_bounds__(256) sgemm_sum_kernel(const int* __restrict__ q_data,
                                                        const float* __restrict__ W_summary) {
    const int K = 256, N = 128;
    __shared__ float As[8][256];   // duplicated
    __shared__ float Bs[8][128];
    __shared__ int qrow_s[128];
    int tid = threadIdx.x;
    int row0 = blockIdx.x * 128;
    if (tid < 128) qrow_s[tid] = q_data[row0 + tid];
    int aRow = tid >> 1, aK4 = (tid & 1) * 4;
    int bK = tid >> 5, bCol = (tid & 31) * 4;
    int tx = tid & 15, ty = tid >> 4;
    ull acc2[8][4];
    #pragma unroll
    for (int i = 0; i < 8; i++)
        #pragma unroll
        for (int j = 0; j < 4; j++) acc2[i][j] = 0ull;

    const float* A = g_read;
    for (int k0 = 0; k0 < K; k0 += 8) {
        float4 av = __ldg((const float4*)(A + (size_t)(row0 + aRow) * K + k0 + aK4));
        *(float2*)&As[aK4 + 0][2 * aRow] = make_float2(av.x, av.x);
        *(float2*)&As[aK4 + 1][2 * aRow] = make_float2(av.y, av.y);
        *(float2*)&As[aK4 + 2][2 * aRow] = make_float2(av.z, av.z);
        *(float2*)&As[aK4 + 3][2 * aRow] = make_float2(av.w, av.w);
        *(float4*)&Bs[bK][bCol] = __ldg((const float4*)(W_summary + (k0 + bK) * N + bCol));
        __syncthreads();
        #pragma unroll
        for (int kk = 0; kk < 8; kk++) {
            ull ra[8], rb[4];
            #pragma unroll
            for (int i = 0; i < 8; i++) ra[i] = *(const ull*)&As[kk][2 * (ty * 8 + i)];
            #pragma unroll
            for (int jp = 0; jp < 4; jp++) rb[jp] = *(const ull*)&Bs[kk][jp * 32 + tx * 2];
            #pragma unroll
            for (int i = 0; i < 8; i++)
                #pragma unroll
                for (int jp = 0; jp < 4; jp++)
                    acc2[i][jp] = fma2(ra[i], rb[jp], acc2[i][jp]);
        }
        __syncthreads();
    }
    #pragma unroll
    for (int i = 0; i < 8; i++) {
        int rl = ty * 8 + i;
        int r = row0 + rl;
        int q = qrow_s[rl];
        const float* qs = g_QStab + q * FDIM;
        #pragma unroll
        for (int jp = 0; jp < 4; jp++) {
            int c = jp * 32 + tx * 2;
            float lo, hi; unpack2(acc2[i][jp], lo, hi);
            *(float2*)&g_summary[(size_t)r * N + c] =
                make_float2(tanhf(lo + __ldg(qs + c)), tanhf(hi + __ldg(qs + c + 1)));
        }
    }
}

// ---------------- K5: per-token head (theta/alpha/CORAL), 32 tokens/warp -----
__global__ void __launch_bounds__(256) head_kernel(const int* __restrict__ q_data,
                                                   const float* __restrict__ W_theta,
                                                   const float* __restrict__ b_theta,
                                                   const float* __restrict__ W_disc,
                                                   const float* __restrict__ b_disc,
                                                   const float* __restrict__ W_c1,
                                                   const float* __restrict__ b_c1,
                                                   const float* __restrict__ W_c2,
                                                   const float* __restrict__ b_c2,
                                                   const float* __restrict__ coral_w,
                                                   const float* __restrict__ coral_b,
                                                   float* __restrict__ out) {
    __shared__ float sWc1[5 * 64], sBc1[64], sWc2[64 * 32], sBc2[32], sCw[32];
    __shared__ float sWth[128], sWd[128];
    __shared__ float h1s[8][64];
    int tid = threadIdx.x;
    for (int i = tid; i < 320; i += 256) sWc1[i] = W_c1[i];
    for (int i = tid; i < 2048; i += 256) sWc2[i] = W_c2[i];
    if (tid < 64) sBc1[tid] = b_c1[tid];
    if (tid < 32) { sBc2[tid] = b_c2[tid]; sCw[tid] = coral_w[tid]; }
    if (tid < 128) { sWth[tid] = W_theta[tid]; sWd[tid] = W_disc[tid]; }
    __syncthreads();

    int warp = tid >> 5, lane = tid & 31;
    float bth = b_theta[0], bd = b_disc[0];
    float cb0 = coral_b[0], cb1 = coral_b[1], cb2 = coral_b[2];
    float wth0 = sWth[lane], wth1 = sWth[lane + 32], wth2 = sWth[lane + 64], wth3 = sWth[lane + 96];
    float wd0 = sWd[lane], wd1 = sWd[lane + 32], wd2 = sWd[lane + 64], wd3 = sWd[lane + 96];
    float cw = sCw[lane];

    const int TOK = 32;
    size_t base = ((size_t)blockIdx.x * 8 + warp) * TOK;
    for (int t = 0; t < TOK; t++) {
        size_t n = base + t;
        const float* srow = g_summary + n * FDIM;
        float s0 = __ldg(srow + lane), s1 = __ldg(srow + lane + 32);
        float s2 = __ldg(srow + lane + 64), s3 = __ldg(srow + lane + 96);
        float th = s0 * wth0 + s1 * wth1 + s2 * wth2 + s3 * wth3;
        float dp = s0 * wd0 + s1 * wd1 + s2 * wd2 + s3 * wd3;
        #pragma unroll
        for (int o = 16; o; o >>= 1) {
            th += __shfl_xor_sync(0xffffffffu, th, o);
            dp += __shfl_xor_sync(0xffffffffu, dp, o);
        }
        float theta = (th + bth) * 3.0f;
        int q = q_data[n];
        float alpha = softplusf_(dp + g_qdtab[q] + bd);
        float be0 = g_betatab[q * 3 + 0];
        float be1 = g_betatab[q * 3 + 1];
        float be2 = g_betatab[q * 3 + 2];
        float feat[5] = {theta, alpha, be0, be1, be2};

        float h1a = sBc1[lane], h1b = sBc1[lane + 32];
        #pragma unroll
        for (int i = 0; i < 5; i++) {
            h1a = fmaf(feat[i], sWc1[i * 64 + lane], h1a);
            h1b = fmaf(feat[i], sWc1[i * 64 + lane + 32], h1b);
        }
        h1s[warp][lane] = fmaxf(h1a, 0.0f);
        h1s[warp][lane + 32] = fmaxf(h1b, 0.0f);
        __syncwarp();
        float h2 = sBc2[lane];
        #pragma unroll
        for (int i = 0; i < 64; i++) h2 = fmaf(h1s[warp][i], sWc2[i * 32 + lane], h2);
        h2 = fmaxf(h2, 0.0f);
        float lg = h2 * cw;
        #pragma unroll
        for (int o = 16; o; o >>= 1) lg += __shfl_xor_sync(0xffffffffu, lg, o);

        if (lane == 0) {
            float l0 = lg + cb0, l1 = lg + cb1, l2 = lg + cb2;
            float c1 = sigmoidf_(l0);
            float c2 = c1 * sigmoidf_(l1);
            float c3 = c2 * sigmoidf_(l2);
            const size_t N = NT;
            out[n] = theta;
            out[N + n * 3 + 0] = be0;
            out[N + n * 3 + 1] = be1;
            out[N + n * 3 + 2] = be2;
            out[4 * N + n] = alpha;
            out[5 * N + n * 4 + 0] = 1.0f - c1;
            out[5 * N + n * 4 + 1] = c1 - c2;
            out[5 * N + n * 4 + 2] = c2 - c3;
            out[5 * N + n * 4 + 3] = c3;
            out[9 * N + n * 3 + 0] = l0;
            out[9 * N + n * 3 + 1] = l1;
            out[9 * N + n * 3 + 2] = l2;
        }
        __syncwarp();
    }
}

// ---------------- launch -----------------------------------------------------
extern "C" void kernel_launch(void* const* d_in, const int* in_sizes, int n_in,
                              void* d_out, int out_size) {
    const int*   q_data   = (const int*)d_in[0];
    const int*   r_data   = (const int*)d_in[1];
    const float* qe_table = (const float*)d_in[2];
    const float* key_mem  = (const float*)d_in[3];
    const float* initMv   = (const float*)d_in[4];
    const float* W_value  = (const float*)d_in[5];
    const float* b_value  = (const float*)d_in[6];
    const float* W_erase  = (const float*)d_in[7];
    const float* b_erase  = (const float*)d_in[8];
    const float* W_add    = (const float*)d_in[9];
    const float* b_add    = (const float*)d_in[10];
    const float* W_summary= (const float*)d_in[11];
    const float* b_summary= (const float*)d_in[12];
    const float* W_theta  = (const float*)d_in[13];
    const float* b_theta  = (const float*)d_in[14];
    const float* W_beta   = (const float*)d_in[15];
    const float* b_beta   = (const float*)d_in[16];
    const float* W_disc   = (const float*)d_in[17];
    const float* b_disc   = (const float*)d_in[18];
    const float* W_c1     = (const float*)d_in[19];
    const float* b_c1     = (const float*)d_in[20];
    const float* W_c2     = (const float*)d_in[21];
    const float* b_c2     = (const float*)d_in[22];
    const float* coral_w  = (const float*)d_in[23];
    const float* coral_b  = (const float*)d_in[24];
    float* out = (float*)d_out;

    // L1: wtab + perq
    wtab_perq_kernel<<<QMAX, 128>>>(qe_table, key_mem, W_summary, b_summary,
                                    W_beta, b_beta, W_disc);
    // L2 (tiny): bv bias + EA row 0
    bv_ea0_kernel<<<1, 128>>>(b_value, W_erase, W_add, b_erase, b_add);
    // L3: fused PP GEMM + EA table
    {
        dim3 g(4, 79);
        ppea_kernel<<<g, 256>>>(W_value, W_erase, W_add);
    }
    // L4: scan (<- ncu capture slot)
    scan_kernel<<<BB, 512>>>(q_data, r_data, initMv);
    // L5: summary GEMM
    sgemm_sum_kernel<<<NT / 128, 256>>>(q_data, W_summary);
    // L6: head
    head_kernel<<<NT / (8 * 32), 256>>>(q_data, W_theta, b_theta, W_disc, b_disc,
                                        W_c1, b_c1, W_c2, b_c2, coral_w, coral_b, out);
}

// round 15
// speedup vs baseline: 1.9051x; 1.1565x over previous
#include <cuda_runtime.h>
#include <math.h>

// Problem dims
#define BB 128
#define SS 1024
#define QMAX 5001          // q ids 0..5000
#define MSLOT 64
#define KDIM 128
#define VDIM 256
#define FDIM 128
#define NT 131072          // BB*SS

typedef unsigned long long ull;

// ---------------- scratch (static device arrays: no allocation) -------------
__device__ float g_Wtab[QMAX * MSLOT];          // softmax(qe @ K^T) per q
__device__ float g_bvE2[512];                   // b_value@[We|Wa] + [b_erase|b_add]
__device__ float g_EAtab[QMAX * 4 * 512];       // [q][r][ erase(256) | add(256) ]
__device__ float g_QStab[QMAX * FDIM];          // qe @ W_summary[256:384] + b_summary
__device__ float g_betatab[QMAX * 3];           // qe @ W_beta + b_beta
__device__ float g_qdtab[QMAX];                 // qe @ W_disc[128:256]
__device__ float g_read[(size_t)NT * VDIM];     // per-step memory reads
__device__ float g_summary[(size_t)NT * FDIM];  // tanh summary

// ---------------- packed f32x2 helpers --------------------------------------
__device__ __forceinline__ ull pack2(float lo, float hi) {
    ull d; asm("mov.b64 %0, {%1, %2};" : "=l"(d) : "f"(lo), "f"(hi)); return d;
}
__device__ __forceinline__ void unpack2(ull v, float& lo, float& hi) {
    asm("mov.b64 {%0, %1}, %2;" : "=f"(lo), "=f"(hi) : "l"(v));
}
__device__ __forceinline__ ull fma2(ull a, ull b, ull c) {
    ull d; asm("fma.rn.f32x2 %0, %1, %2, %3;" : "=l"(d) : "l"(a), "l"(b), "l"(c));
    return d;
}

__device__ __forceinline__ float sigmoidf_(float x) { return 1.0f / (1.0f + expf(-x)); }
__device__ __forceinline__ float softplusf_(float x) {
    return fmaxf(x, 0.0f) + log1pf(expf(-fabsf(x)));
}

// ---------------- K1: wtab + perq, key_memory staged in padded smem ----------
// grid = 640, each CTA handles 8 consecutive q. 128 threads.
#define QPER 8
__global__ void __launch_bounds__(128) wtab_perq_kernel(const float* __restrict__ qe_table,
                                                        const float* __restrict__ key_memory,
                                                        const float* __restrict__ W_summary,
                                                        const float* __restrict__ b_summary,
                                                        const float* __restrict__ W_beta,
                                                        const float* __restrict__ b_beta,
                                                        const float* __restrict__ W_disc) {
    const int t = threadIdx.x;
    __shared__ float skey[MSLOT * 129];   // padded: bank = (m + k) % 32, conflict-free
    __shared__ float qe[KDIM];
    __shared__ float sh_d[MSLOT];
    __shared__ float sh_e[MSLOT];

    // stage key_memory (coalesced LDG, amortized over QPER q's)
    for (int i = t; i < MSLOT * KDIM; i += 128) {
        int row = i >> 7, col = i & 127;
        skey[row * 129 + col] = key_memory[i];
    }

    int q0 = blockIdx.x * QPER;
    int qend = min(q0 + QPER, QMAX);
    float bsum_t = b_summary[t];

    for (int q = q0; q < qend; q++) {
        __syncthreads();               // protects qe/sh_e reuse + first-iter skey
        qe[t] = qe_table[q * KDIM + t];
        __syncthreads();
        if (t < MSLOT) {
            float d = 0.0f;
            #pragma unroll 8
            for (int k = 0; k < KDIM; k++) d = fmaf(qe[k], skey[t * 129 + k], d);
            sh_d[t] = d;
        }
        __syncthreads();
        if (t < MSLOT) {
            float mx = -1e30f;
            #pragma unroll 8
            for (int i = 0; i < MSLOT; i++) mx = fmaxf(mx, sh_d[i]);
            sh_e[t] = expf(sh_d[t] - mx);
        }
        __syncthreads();
        if (t < MSLOT) {
            float sum = 0.0f;
            #pragma unroll 8
            for (int i = 0; i < MSLOT; i++) sum += sh_e[i];
            g_Wtab[q * MSLOT + t] = sh_e[t] / sum;
        }
        // perq projections (W_summary reads are lane-coalesced per dd)
        {
            float acc = bsum_t;
            #pragma unroll 8
            for (int dd = 0; dd < KDIM; dd++)
                acc = fmaf(qe[dd], W_summary[(256 + dd) * FDIM + t], acc);
            g_QStab[q * FDIM + t] = acc;
        }
        if (t < 3) {
            float a = b_beta[t];
            for (int dd = 0; dd < KDIM; dd++) a = fmaf(qe[dd], W_beta[dd * 3 + t], a);
            g_betatab[q * 3 + t] = a;
        } else if (t == 4) {
            float a = 0.0f;
            for (int dd = 0; dd < KDIM; dd++) a = fmaf(qe[dd], W_disc[128 + dd], a);
            g_qdtab[q] = a;
        }
    }
}

// ---------------- K1b (tiny): bv bias row + EAtab[q=0] -----------------------
__global__ void __launch_bounds__(128) bv_ea0_kernel(const float* __restrict__ b_value,
                                                     const float* __restrict__ W_erase,
                                                     const float* __restrict__ W_add,
                                                     const float* __restrict__ b_erase,
                                                     const float* __restrict__ b_add) {
    int t = threadIdx.x;
    for (int j = t; j < 512; j += 128) {
        const float* W = (j < 256) ? (W_erase + j) : (W_add + (j - 256));
        float a = 0.0f;
        for (int k = 0; k < 256; k++) a = fmaf(b_value[k], W[k * 256], a);
        float bias = (j < 256) ? b_erase[j] : b_add[j - 256];
        float x = a + bias;
        g_bvE2[j] = x;
        float act = (j < 256) ? sigmoidf_(x) : tanhf(x);
        #pragma unroll
        for (int rr = 0; rr < 4; rr++) g_EAtab[(size_t)rr * 512 + j] = act;
    }
}

// ---------------- K2: fused PP-GEMM + EA table -------------------------------
// C1[q,:] = Wv[q]·[We|Wa], C2[q,:] = Wv[5000+q]·[We|Wa]  (q = q_id-1, 0..4999)
// EA[q+1][r][col] = act( C1 + bvE2 + (r/3)·C2 )
__global__ void __launch_bounds__(256, 2) ppea_kernel(const float* __restrict__ Wv,
                                                      const float* __restrict__ We,
                                                      const float* __restrict__ Wa) {
    const int K = 256;
    __shared__ float As1[8][128];  // duplicated pairs: 64 rows
    __shared__ float As2[8][128];
    __shared__ float Bs[8][128];
    int tid = threadIdx.x;
    int row0 = blockIdx.y * 64, col0 = blockIdx.x * 128;
    int lrow = (tid & 127) >> 1, ak4 = (tid & 1) * 4;
    int bK = tid >> 5, bCol = (tid & 31) * 4;
    int tx = tid & 15, ty = tid >> 4;
    ull acc1[4][4], acc2[4][4];
    #pragma unroll
    for (int i = 0; i < 4; i++)
        #pragma unroll
        for (int j = 0; j < 4; j++) { acc1[i][j] = 0ull; acc2[i][j] = 0ull; }

    int gr = row0 + lrow;
    bool valid = (gr < 5000);
    const float* aptr = Wv + ((tid < 128) ? (size_t)gr * K : (size_t)(5000 + gr) * K);
    for (int k0 = 0; k0 < K; k0 += 8) {
        float4 av = make_float4(0, 0, 0, 0);
        if (valid) av = __ldg((const float4*)(aptr + k0 + ak4));
        float (*As)[128] = (tid < 128) ? As1 : As2;
        *(float2*)&As[ak4 + 0][2 * lrow] = make_float2(av.x, av.x);
        *(float2*)&As[ak4 + 1][2 * lrow] = make_float2(av.y, av.y);
        *(float2*)&As[ak4 + 2][2 * lrow] = make_float2(av.z, av.z);
        *(float2*)&As[ak4 + 3][2 * lrow] = make_float2(av.w, av.w);
        int j = col0 + bCol;
        const float* bp = (j < 256) ? (We + (k0 + bK) * 256 + j)
                                    : (Wa + (k0 + bK) * 256 + (j - 256));
        *(float4*)&Bs[bK][bCol] = __ldg((const float4*)bp);
        __syncthreads();
        #pragma unroll
        for (int kk = 0; kk < 8; kk++) {
            ull ra1[4], ra2[4], rb[4];
            #pragma unroll
            for (int i = 0; i < 4; i++) {
                ra1[i] = *(const ull*)&As1[kk][2 * (ty * 4 + i)];
                ra2[i] = *(const ull*)&As2[kk][2 * (ty * 4 + i)];
            }
            #pragma unroll
            for (int jp = 0; jp < 4; jp++) rb[jp] = *(const ull*)&Bs[kk][jp * 32 + tx * 2];
            #pragma unroll
            for (int i = 0; i < 4; i++)
                #pragma unroll
                for (int jp = 0; jp < 4; jp++) {
                    acc1[i][jp] = fma2(ra1[i], rb[jp], acc1[i][jp]);
                    acc2[i][jp] = fma2(ra2[i], rb[jp], acc2[i][jp]);
                }
        }
        __syncthreads();
    }
    bool is_erase = (col0 < 256);
    #pragma unroll
    for (int i = 0; i < 4; i++) {
        int row = ty * 4 + i;
        int q = row0 + row;            // q_id - 1
        if (q >= 5000) continue;
        #pragma unroll
        for (int jp = 0; jp < 4; jp++) {
            int c = col0 + jp * 32 + tx * 2;
            float c1lo, c1hi, c2lo, c2hi;
            unpack2(acc1[i][jp], c1lo, c1hi);
            unpack2(acc2[i][jp], c2lo, c2hi);
            float blo = g_bvE2[c], bhi = g_bvE2[c + 1];
            float x1lo = c1lo + blo, x1hi = c1hi + bhi;
            #pragma unroll
            for (int rr = 0; rr < 4; rr++) {
                float sc = (float)rr * (1.0f / 3.0f);
                float xlo = fmaf(sc, c2lo, x1lo);
                float xhi = fmaf(sc, c2hi, x1hi);
                float olo = is_erase ? sigmoidf_(xlo) : tanhf(xlo);
                float ohi = is_erase ? sigmoidf_(xhi) : tanhf(xhi);
                *(float2*)&g_EAtab[((size_t)(q + 1) * 4 + rr) * 512 + c] = make_float2(olo, ohi);
            }
        }
    }
}

// ---------------- K3: persistent recurrence scan (ring + W reg pipeline) -----
// 128 CTAs, 512 threads. Thread owns 2 v (2p, 2p+1) x 16 m (8 pairs).
// quarter = tid&3 (m range quarter*16..+16), p = tid>>2.
// W for step s+1 is LDS-prefetched into registers during step s (ping-pong).
__device__ __forceinline__ void ea_pref(int q, int r, int p, float2& ee, float2& aa) {
    const float* ea = g_EAtab + (size_t)(q * 4 + r) * 512;
    ee = __ldg((const float2*)(ea + 2 * p));
    aa = __ldg((const float2*)(ea + 256 + 2 * p));
}

__device__ __forceinline__ void ldW(ull* W, const float* src) {
    const ulonglong2* wp = (const ulonglong2*)src;
    ulonglong2 t0 = wp[0], t1 = wp[1], t2 = wp[2], t3 = wp[3];
    W[0] = t0.x; W[1] = t0.y; W[2] = t1.x; W[3] = t1.y;
    W[4] = t2.x; W[5] = t2.y; W[6] = t3.x; W[7] = t3.y;
}

__device__ __forceinline__ void scan_step(ull* R0, ull* R1, const ull* W,
                                          float2 ee, float2 aa,
                                          int quarter, float* outp) {
    ull ne0 = pack2(-ee.x, -ee.x), ne1 = pack2(-ee.y, -ee.y);
    ull a20 = pack2(aa.x, aa.x),   a21 = pack2(aa.y, aa.y);
    ull acc0a = 0ull, acc0b = 0ull, acc1a = 0ull, acc1b = 0ull;
    #pragma unroll
    for (int i = 0; i < 4; i++) {
        ull t0 = fma2(ne0, R0[i], a20);
        ull t1 = fma2(ne1, R1[i], a21);
        acc0a = fma2(W[i], R0[i], acc0a);
        acc1a = fma2(W[i], R1[i], acc1a);
        R0[i] = fma2(W[i], t0, R0[i]);
        R1[i] = fma2(W[i], t1, R1[i]);
    }
    #pragma unroll
    for (int i = 4; i < 8; i++) {
        ull t0 = fma2(ne0, R0[i], a20);
        ull t1 = fma2(ne1, R1[i], a21);
        acc0b = fma2(W[i], R0[i], acc0b);
        acc1b = fma2(W[i], R1[i], acc1b);
        R0[i] = fma2(W[i], t0, R0[i]);
        R1[i] = fma2(W[i], t1, R1[i]);
    }
    float x0a, y0a, x0b, y0b, x1a, y1a, x1b, y1b;
    unpack2(acc0a, x0a, y0a); unpack2(acc0b, x0b, y0b);
    unpack2(acc1a, x1a, y1a); unpack2(acc1b, x1b, y1b);
    float rd0 = (x0a + x0b) + (y0a + y0b);
    float rd1 = (x1a + x1b) + (y1a + y1b);
    rd0 += __shfl_xor_sync(0xffffffffu, rd0, 1);
    rd0 += __shfl_xor_sync(0xffffffffu, rd0, 2);
    rd1 += __shfl_xor_sync(0xffffffffu, rd1, 1);
    rd1 += __shfl_xor_sync(0xffffffffu, rd1, 2);
    if (quarter == 0) *(float2*)outp = make_float2(rd0, rd1);
}

__global__ void __launch_bounds__(512) scan_kernel(const int* __restrict__ q_data,
                                                   const int* __restrict__ r_data,
                                                   const float* __restrict__ initMv) {
    const int b = blockIdx.x;
    const int tid = threadIdx.x;
    const int quarter = tid & 3;
    const int p = tid >> 2;

    __shared__ int q_sh[SS + 8];
    __shared__ int r_sh[SS + 8];
    __shared__ float wring[64 * MSLOT];   // 64 steps x 64 floats = 16KB

    for (int i = tid; i < SS; i += 512) {
        q_sh[i] = q_data[b * SS + i];
        r_sh[i] = r_data[b * SS + i];
    }
    if (tid < 8) {
        q_sh[SS + tid] = q_data[b * SS + SS - 1];
        r_sh[SS + tid] = r_data[b * SS + SS - 1];
    }

    ull R0[8], R1[8];
    #pragma unroll
    for (int i = 0; i < 8; i++) {
        int m = quarter * 16 + 2 * i;
        R0[i] = pack2(initMv[m * VDIM + 2 * p],     initMv[(m + 1) * VDIM + 2 * p]);
        R1[i] = pack2(initMv[m * VDIM + 2 * p + 1], initMv[(m + 1) * VDIM + 2 * p + 1]);
    }
    __syncthreads();

    float2 eA, aA, eB, aB, eC, aC, eD, aD;
    ea_pref(q_sh[0], r_sh[0], p, eA, aA);
    ea_pref(q_sh[1], r_sh[1], p, eB, aB);
    ea_pref(q_sh[2], r_sh[2], p, eC, aC);

    float* rdbase = g_read + (((size_t)b << 10)) * VDIM + 2 * p;
    const int qoff = quarter * 16;

    ull W0[8], W1[8];

    #pragma unroll 1
    for (int c = 0; c < 16; c++) {
        __syncthreads();   // prior chunk fully consumed before ring overwrite
        {   // cooperative refill: 64 steps x 64 floats, 2 float4 per thread
            int u = tid * 2;
            int sl = u >> 4;
            int fi = u & 15;
            const float* src = g_Wtab + q_sh[c * 64 + sl] * MSLOT;
            *(float4*)&wring[sl * MSLOT + fi * 4]       = __ldg((const float4*)(src + fi * 4));
            *(float4*)&wring[sl * MSLOT + (fi + 1) * 4] = __ldg((const float4*)(src + (fi + 1) * 4));
        }
        __syncthreads();
        int base = c * 64;
        ldW(W0, &wring[qoff]);   // slot 0 of chunk
        #pragma unroll 1
        for (int k = 0; k < 16; k++) {
            int s = base + 4 * k;
            int sl = 4 * k;
            ldW(W1, &wring[(sl + 1) * MSLOT + qoff]);
            ea_pref(q_sh[s + 3], r_sh[s + 3], p, eD, aD);
            scan_step(R0, R1, W0, eA, aA, quarter, rdbase + (size_t)s * VDIM);

            ldW(W0, &wring[(sl + 2) * MSLOT + qoff]);
            ea_pref(q_sh[s + 4], r_sh[s + 4], p, eA, aA);
            scan_step(R0, R1, W1, eB, aB, quarter, rdbase + (size_t)(s + 1) * VDIM);

            ldW(W1, &wring[(sl + 3) * MSLOT + qoff]);
            ea_pref(q_sh[s + 5], r_sh[s + 5], p, eB, aB);
            scan_step(R0, R1, W0, eC, aC, quarter, rdbase + (size_t)(s + 2) * VDIM);

            ldW(W0, &wring[((sl + 4) & 63) * MSLOT + qoff]);  // wraps harmlessly at chunk end
            ea_pref(q_sh[s + 6], r_sh[s + 6], p, eC, aC);
            scan_step(R0, R1, W1, eD, aD, quarter, rdbase + (size_t)(s + 3) * VDIM);
        }
    }
}

// ---------------- K4: summary SGEMM (131072x256 @ 256x128), f32x2, tanh ------
__global__ void __launch_bounds__(256) sgemm_sum_kernel(const int* __restrict__ q_data,
                                                        const float* __restrict__ W_summary) {
    const int K = 256, N = 128;
    __shared__ float As[8][256];   // duplicated
    __shared__ float Bs[8][128];
    __shared__ int qrow_s[128];
    int tid = threadIdx.x;
    int row0 = blockIdx.x * 128;
    if (tid < 128) qrow_s[tid] = q_data[row0 + tid];
    int aRow = tid >> 1, aK4 = (tid & 1) * 4;
    int bK = tid >> 5, bCol = (tid & 31) * 4;
    int tx = tid & 15, ty = tid >> 4;
    ull acc2[8][4];
    #pragma unroll
    for (int i = 0; i < 8; i++)
        #pragma unroll
        for (int j = 0; j < 4; j++) acc2[i][j] = 0ull;

    const float* A = g_read;
    for (int k0 = 0; k0 < K; k0 += 8) {
        float4 av = __ldg((const float4*)(A + (size_t)(row0 + aRow) * K + k0 + aK4));
        *(float2*)&As[aK4 + 0][2 * aRow] = make_float2(av.x, av.x);
        *(float2*)&As[aK4 + 1][2 * aRow] = make_float2(av.y, av.y);
        *(float2*)&As[aK4 + 2][2 * aRow] = make_float2(av.z, av.z);
        *(float2*)&As[aK4 + 3][2 * aRow] = make_float2(av.w, av.w);
        *(float4*)&Bs[bK][bCol] = __ldg((const float4*)(W_summary + (k0 + bK) * N + bCol));
        __syncthreads();
        #pragma unroll
        for (int kk = 0; kk < 8; kk++) {
            ull ra[8], rb[4];
            #pragma unroll
            for (int i = 0; i < 8; i++) ra[i] = *(const ull*)&As[kk][2 * (ty * 8 + i)];
            #pragma unroll
            for (int jp = 0; jp < 4; jp++) rb[jp] = *(const ull*)&Bs[kk][jp * 32 + tx * 2];
            #pragma unroll
            for (int i = 0; i < 8; i++)
                #pragma unroll
                for (int jp = 0; jp < 4; jp++)
                    acc2[i][jp] = fma2(ra[i], rb[jp], acc2[i][jp]);
        }
        __syncthreads();
    }
    #pragma unroll
    for (int i = 0; i < 8; i++) {
        int rl = ty * 8 + i;
        int r = row0 + rl;
        int q = qrow_s[rl];
        const float* qs = g_QStab + q * FDIM;
        #pragma unroll
        for (int jp = 0; jp < 4; jp++) {
            int c = jp * 32 + tx * 2;
            float lo, hi; unpack2(acc2[i][jp], lo, hi);
            *(float2*)&g_summary[(size_t)r * N + c] =
                make_float2(tanhf(lo + __ldg(qs + c)), tanhf(hi + __ldg(qs + c + 1)));
        }
    }
}

// ---------------- K5: per-token head (theta/alpha/CORAL), 32 tokens/warp -----
__global__ void __launch_bounds__(256) head_kernel(const int* __restrict__ q_data,
                                                   const float* __restrict__ W_theta,
                                                   const float* __restrict__ b_theta,
                                                   const float* __restrict__ W_disc,
                                                   const float* __restrict__ b_disc,
                                                   const float* __restrict__ W_c1,
                                                   const float* __restrict__ b_c1,
                                                   const float* __restrict__ W_c2,
                                                   const float* __restrict__ b_c2,
                                                   const float* __restrict__ coral_w,
                                                   const float* __restrict__ coral_b,
                                                   float* __restrict__ out) {
    __shared__ float sWc1[5 * 64], sBc1[64], sWc2[64 * 32], sBc2[32], sCw[32];
    __shared__ float sWth[128], sWd[128];
    __shared__ float h1s[8][64];
    int tid = threadIdx.x;
    for (int i = tid; i < 320; i += 256) sWc1[i] = W_c1[i];
    for (int i = tid; i < 2048; i += 256) sWc2[i] = W_c2[i];
    if (tid < 64) sBc1[tid] = b_c1[tid];
    if (tid < 32) { sBc2[tid] = b_c2[tid]; sCw[tid] = coral_w[tid]; }
    if (tid < 128) { sWth[tid] = W_theta[tid]; sWd[tid] = W_disc[tid]; }
    __syncthreads();

    int warp = tid >> 5, lane = tid & 31;
    float bth = b_theta[0], bd = b_disc[0];
    float cb0 = coral_b[0], cb1 = coral_b[1], cb2 = coral_b[2];
    float wth0 = sWth[lane], wth1 = sWth[lane + 32], wth2 = sWth[lane + 64], wth3 = sWth[lane + 96];
    float wd0 = sWd[lane], wd1 = sWd[lane + 32], wd2 = sWd[lane + 64], wd3 = sWd[lane + 96];
    float cw = sCw[lane];

    const int TOK = 32;
    size_t base = ((size_t)blockIdx.x * 8 + warp) * TOK;
    for (int t = 0; t < TOK; t++) {
        size_t n = base + t;
        const float* srow = g_summary + n * FDIM;
        float s0 = __ldg(srow + lane), s1 = __ldg(srow + lane + 32);
        float s2 = __ldg(srow + lane + 64), s3 = __ldg(srow + lane + 96);
        float th = s0 * wth0 + s1 * wth1 + s2 * wth2 + s3 * wth3;
        float dp = s0 * wd0 + s1 * wd1 + s2 * wd2 + s3 * wd3;
        #pragma unroll
        for (int o = 16; o; o >>= 1) {
            th += __shfl_xor_sync(0xffffffffu, th, o);
            dp += __shfl_xor_sync(0xffffffffu, dp, o);
        }
        float theta = (th + bth) * 3.0f;
        int q = q_data[n];
        float alpha = softplusf_(dp + g_qdtab[q] + bd);
        float be0 = g_betatab[q * 3 + 0];
        float be1 = g_betatab[q * 3 + 1];
        float be2 = g_betatab[q * 3 + 2];
        float feat[5] = {theta, alpha, be0, be1, be2};

        float h1a = sBc1[lane], h1b = sBc1[lane + 32];
        #pragma unroll
        for (int i = 0; i < 5; i++) {
            h1a = fmaf(feat[i], sWc1[i * 64 + lane], h1a);
            h1b = fmaf(feat[i], sWc1[i * 64 + lane + 32], h1b);
        }
        h1s[warp][lane] = fmaxf(h1a, 0.0f);
        h1s[warp][lane + 32] = fmaxf(h1b, 0.0f);
        __syncwarp();
        float h2 = sBc2[lane];
        #pragma unroll
        for (int i = 0; i < 64; i++) h2 = fmaf(h1s[warp][i], sWc2[i * 32 + lane], h2);
        h2 = fmaxf(h2, 0.0f);
        float lg = h2 * cw;
        #pragma unroll
        for (int o = 16; o; o >>= 1) lg += __shfl_xor_sync(0xffffffffu, lg, o);

        if (lane == 0) {
            float l0 = lg + cb0, l1 = lg + cb1, l2 = lg + cb2;
            float c1 = sigmoidf_(l0);
            float c2 = c1 * sigmoidf_(l1);
            float c3 = c2 * sigmoidf_(l2);
            const size_t N = NT;
            out[n] = theta;
            out[N + n * 3 + 0] = be0;
            out[N + n * 3 + 1] = be1;
            out[N + n * 3 + 2] = be2;
            out[4 * N + n] = alpha;
            out[5 * N + n * 4 + 0] = 1.0f - c1;
            out[5 * N + n * 4 + 1] = c1 - c2;
            out[5 * N + n * 4 + 2] = c2 - c3;
            out[5 * N + n * 4 + 3] = c3;
            out[9 * N + n * 3 + 0] = l0;
            out[9 * N + n * 3 + 1] = l1;
            out[9 * N + n * 3 + 2] = l2;
        }
        __syncwarp();
    }
}

// ---------------- launch -----------------------------------------------------
extern "C" void kernel_launch(void* const* d_in, const int* in_sizes, int n_in,
                              void* d_out, int out_size) {
    const int*   q_data   = (const int*)d_in[0];
    const int*   r_data   = (const int*)d_in[1];
    const float* qe_table = (const float*)d_in[2];
    const float* key_mem  = (const float*)d_in[3];
    const float* initMv   = (const float*)d_in[4];
    const float* W_value  = (const float*)d_in[5];
    const float* b_value  = (const float*)d_in[6];
    const float* W_erase  = (const float*)d_in[7];
    const float* b_erase  = (const float*)d_in[8];
    const float* W_add    = (const float*)d_in[9];
    const float* b_add    = (const float*)d_in[10];
    const float* W_summary= (const float*)d_in[11];
    const float* b_summary= (const float*)d_in[12];
    const float* W_theta  = (const float*)d_in[13];
    const float* b_theta  = (const float*)d_in[14];
    const float* W_beta   = (const float*)d_in[15];
    const float* b_beta   = (const float*)d_in[16];
    const float* W_disc   = (const float*)d_in[17];
    const float* b_disc   = (const float*)d_in[18];
    const float* W_c1     = (const float*)d_in[19];
    const float* b_c1     = (const float*)d_in[20];
    const float* W_c2     = (const float*)d_in[21];
    const float* b_c2     = (const float*)d_in[22];
    const float* coral_w  = (const float*)d_in[23];
    const float* coral_b  = (const float*)d_in[24];
    float* out = (float*)d_out;

    // L1: wtab + perq (key staged in padded smem, 8 q per CTA)
    wtab_perq_kernel<<<(QMAX + QPER - 1) / QPER, 128>>>(qe_table, key_mem,
                                                        W_summary, b_summary,
                                                        W_beta, b_beta, W_disc);
    // L2 (tiny): bv bias + EA row 0
    bv_ea0_kernel<<<1, 128>>>(b_value, W_erase, W_add, b_erase, b_add);
    // L3: fused PP GEMM + EA table
    {
        dim3 g(4, 79);
        ppea_kernel<<<g, 256>>>(W_value, W_erase, W_add);
    }
    // L4: scan
    scan_kernel<<<BB, 512>>>(q_data, r_data, initMv);
    // L5: summary GEMM
    sgemm_sum_kernel<<<NT / 128, 256>>>(q_data, W_summary);
    // L6: head
    head_kernel<<<NT / (8 * 32), 256>>>(q_data, W_theta, b_theta, W_disc, b_disc,
                                        W_c1, b_c1, W_c2, b_c2, coral_w, coral_b, out);
}

// round 16
// speedup vs baseline: 2.1299x; 1.1180x over previous
#include <cuda_runtime.h>
#include <math.h>

// Problem dims
#define BB 128
#define SS 1024
#define QMAX 5001          // q ids 0..5000
#define MSLOT 64
#define KDIM 128
#define VDIM 256
#define FDIM 128
#define NT 131072          // BB*SS

typedef unsigned long long ull;

// ---------------- scratch (static device arrays: no allocation) -------------
__device__ float g_Wtab[QMAX * MSLOT];          // softmax(qe @ K^T) per q
__device__ float g_bvE2[512];                   // b_value@[We|Wa] + [b_erase|b_add]
__device__ float g_EAtab[QMAX * 4 * 512];       // [q][r][ erase(256) | add(256) ]
__device__ float g_QStab[QMAX * FDIM];          // qe @ W_summary[256:384] + b_summary
__device__ float g_betatab[QMAX * 3];           // qe @ W_beta + b_beta
__device__ float g_qdtab[QMAX];                 // qe @ W_disc[128:256]
__device__ float g_read[(size_t)NT * VDIM];     // per-step memory reads
__device__ float g_thdp[(size_t)NT * 2];        // fused (summary@W_theta, summary@W_disc)

// ---------------- packed f32x2 helpers --------------------------------------
__device__ __forceinline__ ull pack2(float lo, float hi) {
    ull d; asm("mov.b64 %0, {%1, %2};" : "=l"(d) : "f"(lo), "f"(hi)); return d;
}
__device__ __forceinline__ void unpack2(ull v, float& lo, float& hi) {
    asm("mov.b64 {%0, %1}, %2;" : "=f"(lo), "=f"(hi) : "l"(v));
}
__device__ __forceinline__ ull fma2(ull a, ull b, ull c) {
    ull d; asm("fma.rn.f32x2 %0, %1, %2, %3;" : "=l"(d) : "l"(a), "l"(b), "l"(c));
    return d;
}

// 1-MUFU activations
__device__ __forceinline__ float tanh_(float x) {
    float y; asm("tanh.approx.f32 %0, %1;" : "=f"(y) : "f"(x)); return y;
}
__device__ __forceinline__ float sigmoid_(float x) {
    return fmaf(0.5f, tanh_(0.5f * x), 0.5f);
}
__device__ __forceinline__ float softplusf_(float x) {
    return fmaxf(x, 0.0f) + log1pf(expf(-fabsf(x)));
}

// ---------------- K1: wtab + perq (key staged in padded smem); last blk: bv --
#define QPER 8
#define WTAB_BLOCKS ((QMAX + QPER - 1) / QPER)   // 626
__global__ void __launch_bounds__(128) wtab_perq_kernel(const float* __restrict__ qe_table,
                                                        const float* __restrict__ key_memory,
                                                        const float* __restrict__ W_summary,
                                                        const float* __restrict__ b_summary,
                                                        const float* __restrict__ W_beta,
                                                        const float* __restrict__ b_beta,
                                                        const float* __restrict__ W_disc,
                                                        const float* __restrict__ b_value,
                                                        const float* __restrict__ W_erase,
                                                        const float* __restrict__ W_add,
                                                        const float* __restrict__ b_erase,
                                                        const float* __restrict__ b_add) {
    const int t = threadIdx.x;
    if (blockIdx.x == WTAB_BLOCKS) {   // bv role: bvE2 + EAtab[q=0]
        for (int j = t; j < 512; j += 128) {
            const float* W = (j < 256) ? (W_erase + j) : (W_add + (j - 256));
            float a = 0.0f;
            for (int k = 0; k < 256; k++) a = fmaf(b_value[k], W[k * 256], a);
            float bias = (j < 256) ? b_erase[j] : b_add[j - 256];
            float x = a + bias;
            g_bvE2[j] = x;
            float act = (j < 256) ? sigmoid_(x) : tanh_(x);
            #pragma unroll
            for (int rr = 0; rr < 4; rr++) g_EAtab[(size_t)rr * 512 + j] = act;
        }
        return;
    }
    __shared__ float skey[MSLOT * 129];   // padded, conflict-free
    __shared__ float qe[KDIM];
    __shared__ float sh_d[MSLOT];
    __shared__ float sh_e[MSLOT];

    for (int i = t; i < MSLOT * KDIM; i += 128) {
        int row = i >> 7, col = i & 127;
        skey[row * 129 + col] = key_memory[i];
    }

    int q0 = blockIdx.x * QPER;
    int qend = min(q0 + QPER, QMAX);
    float bsum_t = b_summary[t];

    for (int q = q0; q < qend; q++) {
        __syncthreads();
        qe[t] = qe_table[q * KDIM + t];
        __syncthreads();
        if (t < MSLOT) {
            float d = 0.0f;
            #pragma unroll 8
            for (int k = 0; k < KDIM; k++) d = fmaf(qe[k], skey[t * 129 + k], d);
            sh_d[t] = d;
        }
        __syncthreads();
        if (t < MSLOT) {
            float mx = -1e30f;
            #pragma unroll 8
            for (int i = 0; i < MSLOT; i++) mx = fmaxf(mx, sh_d[i]);
            sh_e[t] = expf(sh_d[t] - mx);
        }
        __syncthreads();
        if (t < MSLOT) {
            float sum = 0.0f;
            #pragma unroll 8
            for (int i = 0; i < MSLOT; i++) sum += sh_e[i];
            g_Wtab[q * MSLOT + t] = sh_e[t] / sum;
        }
        {
            float acc = bsum_t;
            #pragma unroll 8
            for (int dd = 0; dd < KDIM; dd++)
                acc = fmaf(qe[dd], W_summary[(256 + dd) * FDIM + t], acc);
            g_QStab[q * FDIM + t] = acc;
        }
        if (t < 3) {
            float a = b_beta[t];
            for (int dd = 0; dd < KDIM; dd++) a = fmaf(qe[dd], W_beta[dd * 3 + t], a);
            g_betatab[q * 3 + t] = a;
        } else if (t == 4) {
            float a = 0.0f;
            for (int dd = 0; dd < KDIM; dd++) a = fmaf(qe[dd], W_disc[128 + dd], a);
            g_qdtab[q] = a;
        }
    }
}

// ---------------- K2: fused PP-GEMM + EA table -------------------------------
__global__ void __launch_bounds__(256, 2) ppea_kernel(const float* __restrict__ Wv,
                                                      const float* __restrict__ We,
                                                      const float* __restrict__ Wa) {
    const int K = 256;
    __shared__ float As1[8][128];  // duplicated pairs: 64 rows
    __shared__ float As2[8][128];
    __shared__ float Bs[8][128];
    int tid = threadIdx.x;
    int row0 = blockIdx.y * 64, col0 = blockIdx.x * 128;
    int lrow = (tid & 127) >> 1, ak4 = (tid & 1) * 4;
    int bK = tid >> 5, bCol = (tid & 31) * 4;
    int tx = tid & 15, ty = tid >> 4;
    ull acc1[4][4], acc2[4][4];
    #pragma unroll
    for (int i = 0; i < 4; i++)
        #pragma unroll
        for (int j = 0; j < 4; j++) { acc1[i][j] = 0ull; acc2[i][j] = 0ull; }

    int gr = row0 + lrow;
    bool valid = (gr < 5000);
    const float* aptr = Wv + ((tid < 128) ? (size_t)gr * K : (size_t)(5000 + gr) * K);
    for (int k0 = 0; k0 < K; k0 += 8) {
        float4 av = make_float4(0, 0, 0, 0);
        if (valid) av = __ldg((const float4*)(aptr + k0 + ak4));
        float (*As)[128] = (tid < 128) ? As1 : As2;
        *(float2*)&As[ak4 + 0][2 * lrow] = make_float2(av.x, av.x);
        *(float2*)&As[ak4 + 1][2 * lrow] = make_float2(av.y, av.y);
        *(float2*)&As[ak4 + 2][2 * lrow] = make_float2(av.z, av.z);
        *(float2*)&As[ak4 + 3][2 * lrow] = make_float2(av.w, av.w);
        int j = col0 + bCol;
        const float* bp = (j < 256) ? (We + (k0 + bK) * 256 + j)
                                    : (Wa + (k0 + bK) * 256 + (j - 256));
        *(float4*)&Bs[bK][bCol] = __ldg((const float4*)bp);
        __syncthreads();
        #pragma unroll
        for (int kk = 0; kk < 8; kk++) {
            ull ra1[4], ra2[4], rb[4];
            #pragma unroll
            for (int i = 0; i < 4; i++) {
                ra1[i] = *(const ull*)&As1[kk][2 * (ty * 4 + i)];
                ra2[i] = *(const ull*)&As2[kk][2 * (ty * 4 + i)];
            }
            #pragma unroll
            for (int jp = 0; jp < 4; jp++) rb[jp] = *(const ull*)&Bs[kk][jp * 32 + tx * 2];
            #pragma unroll
            for (int i = 0; i < 4; i++)
                #pragma unroll
                for (int jp = 0; jp < 4; jp++) {
                    acc1[i][jp] = fma2(ra1[i], rb[jp], acc1[i][jp]);
                    acc2[i][jp] = fma2(ra2[i], rb[jp], acc2[i][jp]);
                }
        }
        __syncthreads();
    }
    bool is_erase = (col0 < 256);
    #pragma unroll
    for (int i = 0; i < 4; i++) {
        int row = ty * 4 + i;
        int q = row0 + row;            // q_id - 1
        if (q >= 5000) continue;
        #pragma unroll
        for (int jp = 0; jp < 4; jp++) {
            int c = col0 + jp * 32 + tx * 2;
            float c1lo, c1hi, c2lo, c2hi;
            unpack2(acc1[i][jp], c1lo, c1hi);
            unpack2(acc2[i][jp], c2lo, c2hi);
            float blo = g_bvE2[c], bhi = g_bvE2[c + 1];
            float x1lo = c1lo + blo, x1hi = c1hi + bhi;
            #pragma unroll
            for (int rr = 0; rr < 4; rr++) {
                float sc = (float)rr * (1.0f / 3.0f);
                float xlo = fmaf(sc, c2lo, x1lo);
                float xhi = fmaf(sc, c2hi, x1hi);
                float olo = is_erase ? sigmoid_(xlo) : tanh_(xlo);
                float ohi = is_erase ? sigmoid_(xhi) : tanh_(xhi);
                *(float2*)&g_EAtab[((size_t)(q + 1) * 4 + rr) * 512 + c] = make_float2(olo, ohi);
            }
        }
    }
}

// ---------------- K3: persistent recurrence scan (ring + W reg pipeline) -----
__device__ __forceinline__ void ea_pref(int q, int r, int p, float2& ee, float2& aa) {
    const float* ea = g_EAtab + (size_t)(q * 4 + r) * 512;
    ee = __ldg((const float2*)(ea + 2 * p));
    aa = __ldg((const float2*)(ea + 256 + 2 * p));
}

__device__ __forceinline__ void ldW(ull* W, const float* src) {
    const ulonglong2* wp = (const ulonglong2*)src;
    ulonglong2 t0 = wp[0], t1 = wp[1], t2 = wp[2], t3 = wp[3];
    W[0] = t0.x; W[1] = t0.y; W[2] = t1.x; W[3] = t1.y;
    W[4] = t2.x; W[5] = t2.y; W[6] = t3.x; W[7] = t3.y;
}

__device__ __forceinline__ void scan_step(ull* R0, ull* R1, const ull* W,
                                          float2 ee, float2 aa,
                                          int quarter, float* outp) {
    ull ne0 = pack2(-ee.x, -ee.x), ne1 = pack2(-ee.y, -ee.y);
    ull a20 = pack2(aa.x, aa.x),   a21 = pack2(aa.y, aa.y);
    ull acc0a = 0ull, acc0b = 0ull, acc1a = 0ull, acc1b = 0ull;
    #pragma unroll
    for (int i = 0; i < 4; i++) {
        ull t0 = fma2(ne0, R0[i], a20);
        ull t1 = fma2(ne1, R1[i], a21);
        acc0a = fma2(W[i], R0[i], acc0a);
        acc1a = fma2(W[i], R1[i], acc1a);
        R0[i] = fma2(W[i], t0, R0[i]);
        R1[i] = fma2(W[i], t1, R1[i]);
    }
    #pragma unroll
    for (int i = 4; i < 8; i++) {
        ull t0 = fma2(ne0, R0[i], a20);
        ull t1 = fma2(ne1, R1[i], a21);
        acc0b = fma2(W[i], R0[i], acc0b);
        acc1b = fma2(W[i], R1[i], acc1b);
        R0[i] = fma2(W[i], t0, R0[i]);
        R1[i] = fma2(W[i], t1, R1[i]);
    }
    float x0a, y0a, x0b, y0b, x1a, y1a, x1b, y1b;
    unpack2(acc0a, x0a, y0a); unpack2(acc0b, x0b, y0b);
    unpack2(acc1a, x1a, y1a); unpack2(acc1b, x1b, y1b);
    float rd0 = (x0a + x0b) + (y0a + y0b);
    float rd1 = (x1a + x1b) + (y1a + y1b);
    rd0 += __shfl_xor_sync(0xffffffffu, rd0, 1);
    rd0 += __shfl_xor_sync(0xffffffffu, rd0, 2);
    rd1 += __shfl_xor_sync(0xffffffffu, rd1, 1);
    rd1 += __shfl_xor_sync(0xffffffffu, rd1, 2);
    if (quarter == 0) *(float2*)outp = make_float2(rd0, rd1);
}

__global__ void __launch_bounds__(512) scan_kernel(const int* __restrict__ q_data,
                                                   const int* __restrict__ r_data,
                                                   const float* __restrict__ initMv) {
    const int b = blockIdx.x;
    const int tid = threadIdx.x;
    const int quarter = tid & 3;
    const int p = tid >> 2;

    __shared__ int q_sh[SS + 8];
    __shared__ int r_sh[SS + 8];
    __shared__ float wring[64 * MSLOT];   // 64 steps x 64 floats = 16KB

    for (int i = tid; i < SS; i += 512) {
        q_sh[i] = q_data[b * SS + i];
        r_sh[i] = r_data[b * SS + i];
    }
    if (tid < 8) {
        q_sh[SS + tid] = q_data[b * SS + SS - 1];
        r_sh[SS + tid] = r_data[b * SS + SS - 1];
    }

    ull R0[8], R1[8];
    #pragma unroll
    for (int i = 0; i < 8; i++) {
        int m = quarter * 16 + 2 * i;
        R0[i] = pack2(initMv[m * VDIM + 2 * p],     initMv[(m + 1) * VDIM + 2 * p]);
        R1[i] = pack2(initMv[m * VDIM + 2 * p + 1], initMv[(m + 1) * VDIM + 2 * p + 1]);
    }
    __syncthreads();

    float2 eA, aA, eB, aB, eC, aC, eD, aD;
    ea_pref(q_sh[0], r_sh[0], p, eA, aA);
    ea_pref(q_sh[1], r_sh[1], p, eB, aB);
    ea_pref(q_sh[2], r_sh[2], p, eC, aC);

    float* rdbase = g_read + (((size_t)b << 10)) * VDIM + 2 * p;
    const int qoff = quarter * 16;

    ull W0[8], W1[8];

    #pragma unroll 1
    for (int c = 0; c < 16; c++) {
        __syncthreads();
        {   // cooperative refill: 64 steps x 64 floats, 2 float4 per thread
            int u = tid * 2;
            int sl = u >> 4;
            int fi = u & 15;
            const float* src = g_Wtab + q_sh[c * 64 + sl] * MSLOT;
            *(float4*)&wring[sl * MSLOT + fi * 4]       = __ldg((const float4*)(src + fi * 4));
            *(float4*)&wring[sl * MSLOT + (fi + 1) * 4] = __ldg((const float4*)(src + (fi + 1) * 4));
        }
        __syncthreads();
        int base = c * 64;
        ldW(W0, &wring[qoff]);
        #pragma unroll 1
        for (int k = 0; k < 16; k++) {
            int s = base + 4 * k;
            int sl = 4 * k;
            ldW(W1, &wring[(sl + 1) * MSLOT + qoff]);
            ea_pref(q_sh[s + 3], r_sh[s + 3], p, eD, aD);
            scan_step(R0, R1, W0, eA, aA, quarter, rdbase + (size_t)s * VDIM);

            ldW(W0, &wring[(sl + 2) * MSLOT + qoff]);
            ea_pref(q_sh[s + 4], r_sh[s + 4], p, eA, aA);
            scan_step(R0, R1, W1, eB, aB, quarter, rdbase + (size_t)(s + 1) * VDIM);

            ldW(W1, &wring[(sl + 3) * MSLOT + qoff]);
            ea_pref(q_sh[s + 5], r_sh[s + 5], p, eB, aB);
            scan_step(R0, R1, W0, eC, aC, quarter, rdbase + (size_t)(s + 2) * VDIM);

            ldW(W0, &wring[((sl + 4) & 63) * MSLOT + qoff]);
            ea_pref(q_sh[s + 6], r_sh[s + 6], p, eC, aC);
            scan_step(R0, R1, W1, eD, aD, quarter, rdbase + (size_t)(s + 3) * VDIM);
        }
    }
}

// ---------------- K4: summary SGEMM + fused theta/disc projection ------------
// summary = tanh(read@Ws + qs); th = summary@W_theta; dp = summary@W_disc.
// Stores only (th, dp) per token -> g_thdp. No 67MB summary round-trip.
__global__ void __launch_bounds__(256) sgemm_sum_kernel(const int* __restrict__ q_data,
                                                        const float* __restrict__ W_summary,
                                                        const float* __restrict__ W_theta,
                                                        const float* __restrict__ W_disc) {
    const int K = 256, N = 128;
    __shared__ float As[8][256];   // duplicated
    __shared__ float Bs[8][128];
    __shared__ int qrow_s[128];
    __shared__ float sWth[128], sWd[128];
    int tid = threadIdx.x;
    int row0 = blockIdx.x * 128;
    if (tid < 128) {
        qrow_s[tid] = q_data[row0 + tid];
        sWth[tid] = W_theta[tid];
        sWd[tid] = W_disc[tid];
    }
    int aRow = tid >> 1, aK4 = (tid & 1) * 4;
    int bK = tid >> 5, bCol = (tid & 31) * 4;
    int tx = tid & 15, ty = tid >> 4;
    ull acc2[8][4];
    #pragma unroll
    for (int i = 0; i < 8; i++)
        #pragma unroll
        for (int j = 0; j < 4; j++) acc2[i][j] = 0ull;

    const float* A = g_read;
    for (int k0 = 0; k0 < K; k0 += 8) {
        float4 av = __ldg((const float4*)(A + (size_t)(row0 + aRow) * K + k0 + aK4));
        *(float2*)&As[aK4 + 0][2 * aRow] = make_float2(av.x, av.x);
        *(float2*)&As[aK4 + 1][2 * aRow] = make_float2(av.y, av.y);
        *(float2*)&As[aK4 + 2][2 * aRow] = make_float2(av.z, av.z);
        *(float2*)&As[aK4 + 3][2 * aRow] = make_float2(av.w, av.w);
        *(float4*)&Bs[bK][bCol] = __ldg((const float4*)(W_summary + (k0 + bK) * N + bCol));
        __syncthreads();
        #pragma unroll
        for (int kk = 0; kk < 8; kk++) {
            ull ra[8], rb[4];
            #pragma unroll
            for (int i = 0; i < 8; i++) ra[i] = *(const ull*)&As[kk][2 * (ty * 8 + i)];
            #pragma unroll
            for (int jp = 0; jp < 4; jp++) rb[jp] = *(const ull*)&Bs[kk][jp * 32 + tx * 2];
            #pragma unroll
            for (int i = 0; i < 8; i++)
                #pragma unroll
                for (int jp = 0; jp < 4; jp++)
                    acc2[i][jp] = fma2(ra[i], rb[jp], acc2[i][jp]);
        }
        __syncthreads();
    }
    // Epilogue: tanh + project to (theta, disc) partials, reduce over 16 tx lanes.
    #pragma unroll
    for (int i = 0; i < 8; i++) {
        int rl = ty * 8 + i;
        int r = row0 + rl;
        int q = qrow_s[rl];
        const float* qs = g_QStab + q * FDIM;
        float thp = 0.0f, dpp = 0.0f;
        #pragma unroll
        for (int jp = 0; jp < 4; jp++) {
            int c = jp * 32 + tx * 2;
            float lo, hi; unpack2(acc2[i][jp], lo, hi);
            float s_lo = tanh_(lo + __ldg(qs + c));
            float s_hi = tanh_(hi + __ldg(qs + c + 1));
            thp = fmaf(s_lo, sWth[c], thp);
            thp = fmaf(s_hi, sWth[c + 1], thp);
            dpp = fmaf(s_lo, sWd[c], dpp);
            dpp = fmaf(s_hi, sWd[c + 1], dpp);
        }
        // reduce over the 16 tx lanes (stay within half-warp)
        #pragma unroll
        for (int o = 8; o; o >>= 1) {
            thp += __shfl_xor_sync(0xffffffffu, thp, o);
            dpp += __shfl_xor_sync(0xffffffffu, dpp, o);
        }
        if (tx == 0) *(float2*)&g_thdp[(size_t)r * 2] = make_float2(thp, dpp);
    }
}

// ---------------- K5: per-token head (theta/alpha/CORAL), 32 tokens/warp -----
__global__ void __launch_bounds__(256) head_kernel(const int* __restrict__ q_data,
                                                   const float* __restrict__ b_theta,
                                                   const float* __restrict__ b_disc,
                                                   const float* __restrict__ W_c1,
                                                   const float* __restrict__ b_c1,
                                                   const float* __restrict__ W_c2,
                                                   const float* __restrict__ b_c2,
                                                   const float* __restrict__ coral_w,
                                                   const float* __restrict__ coral_b,
                                                   float* __restrict__ out) {
    __shared__ float sWc1[5 * 64], sBc1[64], sWc2[64 * 32], sBc2[32], sCw[32];
    __shared__ float h1s[8][64];
    int tid = threadIdx.x;
    for (int i = tid; i < 320; i += 256) sWc1[i] = W_c1[i];
    for (int i = tid; i < 2048; i += 256) sWc2[i] = W_c2[i];
    if (tid < 64) sBc1[tid] = b_c1[tid];
    if (tid < 32) { sBc2[tid] = b_c2[tid]; sCw[tid] = coral_w[tid]; }
    __syncthreads();

    int warp = tid >> 5, lane = tid & 31;
    float bth = b_theta[0], bd = b_disc[0];
    float cb0 = coral_b[0], cb1 = coral_b[1], cb2 = coral_b[2];
    float cw = sCw[lane];

    const int TOK = 32;
    size_t base = ((size_t)blockIdx.x * 8 + warp) * TOK;
    for (int t = 0; t < TOK; t++) {
        size_t n = base + t;
        float2 td = *(const float2*)&g_thdp[n * 2];   // broadcast load
        float theta = (td.x + bth) * 3.0f;
        int q = q_data[n];
        float alpha = softplusf_(td.y + g_qdtab[q] + bd);
        float be0 = g_betatab[q * 3 + 0];
        float be1 = g_betatab[q * 3 + 1];
        float be2 = g_betatab[q * 3 + 2];
        float feat[5] = {theta, alpha, be0, be1, be2};

        float h1a = sBc1[lane], h1b = sBc1[lane + 32];
        #pragma unroll
        for (int i = 0; i < 5; i++) {
            h1a = fmaf(feat[i], sWc1[i * 64 + lane], h1a);
            h1b = fmaf(feat[i], sWc1[i * 64 + lane + 32], h1b);
        }
        h1s[warp][lane] = fmaxf(h1a, 0.0f);
        h1s[warp][lane + 32] = fmaxf(h1b, 0.0f);
        __syncwarp();
        float h2 = sBc2[lane];
        #pragma unroll
        for (int i = 0; i < 64; i++) h2 = fmaf(h1s[warp][i], sWc2[i * 32 + lane], h2);
        h2 = fmaxf(h2, 0.0f);
        float lg = h2 * cw;
        #pragma unroll
        for (int o = 16; o; o >>= 1) lg += __shfl_xor_sync(0xffffffffu, lg, o);

        if (lane == 0) {
            float l0 = lg + cb0, l1 = lg + cb1, l2 = lg + cb2;
            float c1 = sigmoid_(l0);
            float c2 = c1 * sigmoid_(l1);
            float c3 = c2 * sigmoid_(l2);
            const size_t N = NT;
            out[n] = theta;
            out[N + n * 3 + 0] = be0;
            out[N + n * 3 + 1] = be1;
            out[N + n * 3 + 2] = be2;
            out[4 * N + n] = alpha;
            out[5 * N + n * 4 + 0] = 1.0f - c1;
            out[5 * N + n * 4 + 1] = c1 - c2;
            out[5 * N + n * 4 + 2] = c2 - c3;
            out[5 * N + n * 4 + 3] = c3;
            out[9 * N + n * 3 + 0] = l0;
            out[9 * N + n * 3 + 1] = l1;
            out[9 * N + n * 3 + 2] = l2;
        }
        __syncwarp();
    }
}

// ---------------- launch -----------------------------------------------------
extern "C" void kernel_launch(void* const* d_in, const int* in_sizes, int n_in,
                              void* d_out, int out_size) {
    const int*   q_data   = (const int*)d_in[0];
    const int*   r_data   = (const int*)d_in[1];
    const float* qe_table = (const float*)d_in[2];
    const float* key_mem  = (const float*)d_in[3];
    const float* initMv   = (const float*)d_in[4];
    const float* W_value  = (const float*)d_in[5];
    const float* b_value  = (const float*)d_in[6];
    const float* W_erase  = (const float*)d_in[7];
    const float* b_erase  = (const float*)d_in[8];
    const float* W_add    = (const float*)d_in[9];
    const float* b_add    = (const float*)d_in[10];
    const float* W_summary= (const float*)d_in[11];
    const float* b_summary= (const float*)d_in[12];
    const float* W_theta  = (const float*)d_in[13];
    const float* b_theta  = (const float*)d_in[14];
    const float* W_beta   = (const float*)d_in[15];
    const float* b_beta   = (const float*)d_in[16];
    const float* W_disc   = (const float*)d_in[17];
    const float* b_disc   = (const float*)d_in[18];
    const float* W_c1     = (const float*)d_in[19];
    const float* b_c1     = (const float*)d_in[20];
    const float* W_c2     = (const float*)d_in[21];
    const float* b_c2     = (const float*)d_in[22];
    const float* coral_w  = (const float*)d_in[23];
    const float* coral_b  = (const float*)d_in[24];
    float* out = (float*)d_out;

    // L1: wtab + perq + bv
    wtab_perq_kernel<<<WTAB_BLOCKS + 1, 128>>>(qe_table, key_mem, W_summary, b_summary,
                                               W_beta, b_beta, W_disc,
                                               b_value, W_erase, W_add, b_erase, b_add);
    // L2: fused PP GEMM + EA table
    {
        dim3 g(4, 79);
        ppea_kernel<<<g, 256>>>(W_value, W_erase, W_add);
    }
    // L3: scan
    scan_kernel<<<BB, 512>>>(q_data, r_data, initMv);
    // L4: summary GEMM + theta/disc fusion (<- ncu capture slot)
    sgemm_sum_kernel<<<NT / 128, 256>>>(q_data, W_summary, W_theta, W_disc);
    // L5: head
    head_kernel<<<NT / (8 * 32), 256>>>(q_data, b_theta, b_disc,
                                        W_c1, b_c1, W_c2, b_c2, coral_w, coral_b, out);
}